// round 5
// baseline (speedup 1.0000x reference)
#include <cuda_runtime.h>
#include <cstdint>

#define HIDN   2048
#define NH     16
#define NKV    4
#define HD     128
#define INTERN 8192
#define BATCH  4
#define SEQ    1024
#define TTOK   (BATCH*SEQ)   /* 4096 */
#define EPSV   1e-6f
#define QK_SCALE 0.08838834764831845f  /* 1/sqrt(128) */

// ---------------- scratch ----------------
__device__ float g_h   [TTOK * HIDN];
__device__ float g_q   [TTOK * NH  * HD];
__device__ float g_k   [TTOK * NKV * HD];
__device__ float g_v   [TTOK * NKV * HD];
__device__ float g_attn[TTOK * HIDN];
__device__ float g_x1  [TTOK * HIDN];
__device__ float g_gate[TTOK * INTERN];

// ---------------- tf32 mma helpers ----------------
__device__ __forceinline__ uint32_t f2tf(float f) {
    uint32_t u; asm("cvt.rna.tf32.f32 %0, %1;" : "=r"(u) : "f"(f)); return u;
}
__device__ __forceinline__ uint4 f2tf4(float4 v) {
    uint4 u;
    u.x = f2tf(v.x); u.y = f2tf(v.y); u.z = f2tf(v.z); u.w = f2tf(v.w);
    return u;
}
__device__ __forceinline__ void mma_tf32(float c[4], const uint32_t a[4], const uint32_t b[2]) {
    asm volatile("mma.sync.aligned.m16n8k8.row.col.f32.tf32.tf32.f32 "
        "{%0,%1,%2,%3}, {%4,%5,%6,%7}, {%8,%9}, {%0,%1,%2,%3};\n"
        : "+f"(c[0]), "+f"(c[1]), "+f"(c[2]), "+f"(c[3])
        : "r"(a[0]), "r"(a[1]), "r"(a[2]), "r"(a[3]), "r"(b[0]), "r"(b[1]));
}

// ---------------- GEMM body: C[.,ldc] = A[M,K] @ B[N,K]^T + epilogue ----------------
// BM=128, BN=128, BK=32; 256 thr = 8 warps (2M x 4N), warp tile 64x32.
// smem: pre-converted tf32 words, stride 36 (conflict-free frag loads).
// Double-buffered with ONE __syncthreads per k-tile.
// MODE 0: C = acc (+bias)(+res).  MODE 1: C = silu(res)*acc.
#define GSTRIDE 36
#define GBUF    (128 * GSTRIDE)
#define GEMM_SMEM_BYTES (4 * GBUF * 4)

template<int MODE>
__device__ __forceinline__ void gemm_body(
    const float* __restrict__ A, const float* __restrict__ B,
    const float* __restrict__ bias, const float* __restrict__ res,
    float* __restrict__ C, int ldc, int K, int brow, int bcol)
{
    extern __shared__ uint32_t smem[];
    uint32_t* As = smem;
    uint32_t* Bs = smem + 2 * GBUF;

    const int tid  = threadIdx.x;
    const int lane = tid & 31, warp = tid >> 5;
    const int wm = warp & 1, wn = warp >> 1;
    const int g  = lane >> 2, t4 = lane & 3;

    const int lr = tid >> 3;
    const int lc = (tid & 7) << 2;
    const float* aptr = A + (size_t)(brow + lr) * K + lc;
    const float* bptr = B + (size_t)(bcol + lr) * K + lc;
    const int soff = lr * GSTRIDE + lc;

    float acc[4][4][4];
#pragma unroll
    for (int i = 0; i < 4; i++)
#pragma unroll
        for (int j = 0; j < 4; j++)
#pragma unroll
            for (int e = 0; e < 4; e++) acc[i][j][e] = 0.f;

    float4 ra[4], rb[4];
#pragma unroll
    for (int r = 0; r < 4; r++) {
        ra[r] = *(const float4*)(aptr + (size_t)(r * 32) * K);
        rb[r] = *(const float4*)(bptr + (size_t)(r * 32) * K);
    }
#pragma unroll
    for (int r = 0; r < 4; r++) {
        *(uint4*)&As[soff + r * 32 * GSTRIDE] = f2tf4(ra[r]);
        *(uint4*)&Bs[soff + r * 32 * GSTRIDE] = f2tf4(rb[r]);
    }
    __syncthreads();

    const int nk = K >> 5;
    for (int t = 0; t < nk; ++t) {
        const int cur = t & 1;
        if (t + 1 < nk) {
            const float* ap = aptr + (size_t)(t + 1) * 32;
            const float* bp = bptr + (size_t)(t + 1) * 32;
#pragma unroll
            for (int r = 0; r < 4; r++) {
                ra[r] = *(const float4*)(ap + (size_t)(r * 32) * K);
                rb[r] = *(const float4*)(bp + (size_t)(r * 32) * K);
            }
        }
        const uint32_t* As_ = As + cur * GBUF;
        const uint32_t* Bs_ = Bs + cur * GBUF;
#pragma unroll
        for (int kb = 0; kb < 32; kb += 8) {
            uint32_t af[4][4], bf[4][2];
#pragma unroll
            for (int mt = 0; mt < 4; ++mt) {
                int base = (wm * 64 + mt * 16 + g) * GSTRIDE + kb + t4;
                af[mt][0] = As_[base];
                af[mt][1] = As_[base + 8 * GSTRIDE];
                af[mt][2] = As_[base + 4];
                af[mt][3] = As_[base + 8 * GSTRIDE + 4];
            }
#pragma unroll
            for (int nt = 0; nt < 4; ++nt) {
                int nbase = (wn * 32 + nt * 8 + g) * GSTRIDE + kb + t4;
                bf[nt][0] = Bs_[nbase];
                bf[nt][1] = Bs_[nbase + 4];
            }
#pragma unroll
            for (int mt = 0; mt < 4; ++mt)
#pragma unroll
                for (int nt = 0; nt < 4; ++nt)
                    mma_tf32(acc[mt][nt], af[mt], bf[nt]);
        }
        if (t + 1 < nk) {
            uint32_t* An = As + (cur ^ 1) * GBUF;
            uint32_t* Bn = Bs + (cur ^ 1) * GBUF;
#pragma unroll
            for (int r = 0; r < 4; r++) {
                *(uint4*)&An[soff + r * 32 * GSTRIDE] = f2tf4(ra[r]);
                *(uint4*)&Bn[soff + r * 32 * GSTRIDE] = f2tf4(rb[r]);
            }
        }
        __syncthreads();   // single barrier per k-tile
    }

    // epilogue
#pragma unroll
    for (int mt = 0; mt < 4; ++mt) {
        int r0 = brow + wm * 64 + mt * 16 + g;
#pragma unroll
        for (int nt = 0; nt < 4; ++nt) {
            int c0 = bcol + wn * 32 + nt * 8 + t4 * 2;
            float2 v0 = make_float2(acc[mt][nt][0], acc[mt][nt][1]);
            float2 v1 = make_float2(acc[mt][nt][2], acc[mt][nt][3]);
            if (MODE == 1) {
                float2 ga = *(const float2*)&res[(size_t)r0 * ldc + c0];
                float2 gb = *(const float2*)&res[(size_t)(r0 + 8) * ldc + c0];
                v0.x *= ga.x / (1.f + __expf(-ga.x));
                v0.y *= ga.y / (1.f + __expf(-ga.y));
                v1.x *= gb.x / (1.f + __expf(-gb.x));
                v1.y *= gb.y / (1.f + __expf(-gb.y));
            } else {
                if (bias) {
                    float2 bv = *(const float2*)&bias[c0];
                    v0.x += bv.x; v0.y += bv.y; v1.x += bv.x; v1.y += bv.y;
                }
                if (res) {
                    float2 rra = *(const float2*)&res[(size_t)r0 * ldc + c0];
                    float2 rrb = *(const float2*)&res[(size_t)(r0 + 8) * ldc + c0];
                    v0.x += rra.x; v0.y += rra.y; v1.x += rrb.x; v1.y += rrb.y;
                }
            }
            *(float2*)&C[(size_t)r0 * ldc + c0]       = v0;
            *(float2*)&C[(size_t)(r0 + 8) * ldc + c0] = v1;
        }
    }
}

__global__ __launch_bounds__(256, 2)
void gemm_std(const float* __restrict__ A, const float* __restrict__ B,
              const float* __restrict__ bias, const float* __restrict__ res,
              float* __restrict__ C, int ldc, int K) {
    gemm_body<0>(A, B, bias, res, C, ldc, K, blockIdx.y << 7, blockIdx.x << 7);
}

__global__ __launch_bounds__(256, 2)
void gemm_silu(const float* __restrict__ A, const float* __restrict__ B,
               const float* __restrict__ gate, float* __restrict__ C, int ldc, int K) {
    gemm_body<1>(A, B, nullptr, gate, C, ldc, K, blockIdx.y << 7, blockIdx.x << 7);
}

// fused QKV: grid.x = 24 (16 q-blocks, 4 k-blocks, 4 v-blocks)
__global__ __launch_bounds__(256, 2)
void gemm_qkv(const float* __restrict__ h,
              const float* __restrict__ wq, const float* __restrict__ bq,
              const float* __restrict__ wk, const float* __restrict__ bk,
              const float* __restrict__ wv, const float* __restrict__ bv,
              float* __restrict__ q, float* __restrict__ k, float* __restrict__ v) {
    const int cb = blockIdx.x, brow = blockIdx.y << 7;
    if (cb < 16)      gemm_body<0>(h, wq, bq, nullptr, q, NH * HD,  HIDN, brow, cb << 7);
    else if (cb < 20) gemm_body<0>(h, wk, bk, nullptr, k, NKV * HD, HIDN, brow, (cb - 16) << 7);
    else              gemm_body<0>(h, wv, bv, nullptr, v, NKV * HD, HIDN, brow, (cb - 20) << 7);
}

// ---------------- RMSNorm over HIDN=2048 ----------------
__global__ void rmsnorm_kernel(const float* __restrict__ x, const float* __restrict__ w,
                               float* __restrict__ out) {
    int row = blockIdx.x;
    const float* xr = x + (size_t)row * HIDN;
    float4 v[2];
    float ss = 0.f;
#pragma unroll
    for (int i = 0; i < 2; i++) {
        v[i] = *(const float4*)&xr[(threadIdx.x + i * 256) * 4];
        ss += v[i].x * v[i].x + v[i].y * v[i].y + v[i].z * v[i].z + v[i].w * v[i].w;
    }
#pragma unroll
    for (int o = 16; o; o >>= 1) ss += __shfl_xor_sync(~0u, ss, o);
    __shared__ float red[8];
    if ((threadIdx.x & 31) == 0) red[threadIdx.x >> 5] = ss;
    __syncthreads();
    if (threadIdx.x == 0) {
        float t = 0.f;
#pragma unroll
        for (int i = 0; i < 8; i++) t += red[i];
        red[0] = rsqrtf(t / (float)HIDN + EPSV);
    }
    __syncthreads();
    float r = red[0];
#pragma unroll
    for (int i = 0; i < 2; i++) {
        int c = (threadIdx.x + i * 256) * 4;
        float4 wv = *(const float4*)&w[c];
        float4 o4 = make_float4(v[i].x * r * wv.x, v[i].y * r * wv.y,
                                v[i].z * r * wv.z, v[i].w * r * wv.w);
        *(float4*)&out[(size_t)row * HIDN + c] = o4;
    }
}

// ---------------- per-head RMSNorm + RoPE ----------------
__global__ void qknorm_rope_kernel(float* __restrict__ qb, float* __restrict__ kb,
                                   const float* __restrict__ qw, const float* __restrict__ kw,
                                   const float* __restrict__ cs, const float* __restrict__ sn) {
    int token = blockIdx.x, h = blockIdx.y;
    float* p; const float* w;
    if (h < NH) { p = qb + (size_t)token * (NH * HD)  + h * HD;        w = qw; }
    else        { p = kb + (size_t)token * (NKV * HD) + (h - NH) * HD; w = kw; }
    int d = threadIdx.x;
    float v = p[d];
    float ss = v * v;
#pragma unroll
    for (int o = 16; o; o >>= 1) ss += __shfl_xor_sync(~0u, ss, o);
    __shared__ float red[4];
    __shared__ float sh[128];
    if ((d & 31) == 0) red[d >> 5] = ss;
    __syncthreads();
    float tot = red[0] + red[1] + red[2] + red[3];
    float r = rsqrtf(tot / 128.f + EPSV);
    float xn = v * r * w[d];
    sh[d] = xn;
    __syncthreads();
    float rot = (d < 64) ? -sh[d + 64] : sh[d - 64];
    float c = cs[(size_t)token * 128 + d], s = sn[(size_t)token * 128 + d];
    p[d] = xn * c + rot * s;
}

// ---------------- flash attention (fp32, causal, GQA) ----------------
#define ATTN_SMEM_FLOATS (3 * 64 * 132 + 3 * 64)
__global__ __launch_bounds__(256)
void attn_kernel(const float* __restrict__ q, const float* __restrict__ k,
                 const float* __restrict__ v, float* __restrict__ o) {
    extern __shared__ float sm[];
    float* Qs   = sm;
    float* KP   = sm + 64 * 132;
    float* Vs   = sm + 2 * 64 * 132;
    float* Mrow = sm + 3 * 64 * 132;
    float* Lrow = Mrow + 64;
    float* Arow = Lrow + 64;

    const int tid = threadIdx.x;
    const int tr = tid >> 4, tc = tid & 15;
    const int qt = blockIdx.x, hq = blockIdx.y, b = blockIdx.z;
    const int kvh = hq >> 2;
    const int tok0 = b * SEQ + qt * 64;
    const int cA = 4 * tc, cB = 64 + 4 * tc;

    for (int l = tid; l < 2048; l += 256) {
        int r = l >> 5, d4 = (l & 31) * 4;
        float4 qv = *(const float4*)&q[(size_t)(tok0 + r) * (NH * HD) + hq * HD + d4];
        qv.x *= QK_SCALE; qv.y *= QK_SCALE; qv.z *= QK_SCALE; qv.w *= QK_SCALE;
        *(float4*)&Qs[r * 132 + d4] = qv;
    }
    if (tid < 64) { Mrow[tid] = -3.0e38f; Lrow[tid] = 0.f; }
    float O[4][8];
#pragma unroll
    for (int i = 0; i < 4; i++)
#pragma unroll
        for (int m = 0; m < 8; m++) O[i][m] = 0.f;
    __syncthreads();

    for (int kt = 0; kt <= qt; ++kt) {
        for (int l = tid; l < 2048; l += 256) {
            int r = l >> 5, d4 = (l & 31) * 4;
            size_t base = (size_t)(b * SEQ + kt * 64 + r) * (NKV * HD) + kvh * HD + d4;
            *(float4*)&KP[r * 132 + d4] = *(const float4*)&k[base];
            *(float4*)&Vs[r * 132 + d4] = *(const float4*)&v[base];
        }
        __syncthreads();

        float s[4][4];
#pragma unroll
        for (int i = 0; i < 4; i++)
#pragma unroll
            for (int j = 0; j < 4; j++) s[i][j] = 0.f;
        for (int kk = 0; kk < 128; kk += 4) {
            float4 q4[4], k4[4];
#pragma unroll
            for (int i = 0; i < 4; i++) q4[i] = *(const float4*)&Qs[(tr + 16 * i) * 132 + kk];
#pragma unroll
            for (int j = 0; j < 4; j++) k4[j] = *(const float4*)&KP[(tc + 16 * j) * 132 + kk];
#pragma unroll
            for (int i = 0; i < 4; i++)
#pragma unroll
                for (int j = 0; j < 4; j++)
                    s[i][j] += q4[i].x * k4[j].x + q4[i].y * k4[j].y
                             + q4[i].z * k4[j].z + q4[i].w * k4[j].w;
        }
        __syncthreads();

        const bool diag = (kt == qt);
#pragma unroll
        for (int i = 0; i < 4; i++) {
            int rl = tr + 16 * i;
            if (diag) {
#pragma unroll
                for (int j = 0; j < 4; j++)
                    if (tc + 16 * j > rl) s[i][j] = -1.0e30f;
            }
            float mx = fmaxf(fmaxf(s[i][0], s[i][1]), fmaxf(s[i][2], s[i][3]));
#pragma unroll
            for (int off = 1; off < 16; off <<= 1) mx = fmaxf(mx, __shfl_xor_sync(~0u, mx, off));
            float mold = Mrow[rl];
            float mnew = fmaxf(mold, mx);
            float psum = 0.f;
#pragma unroll
            for (int j = 0; j < 4; j++) {
                float p = __expf(s[i][j] - mnew);
                KP[rl * 68 + tc + 16 * j] = p;
                psum += p;
            }
#pragma unroll
            for (int off = 1; off < 16; off <<= 1) psum += __shfl_xor_sync(~0u, psum, off);
            if (tc == 0) {
                float al = __expf(mold - mnew);
                Mrow[rl] = mnew;
                Lrow[rl] = Lrow[rl] * al + psum;
                Arow[rl] = al;
            }
        }
        __syncthreads();

#pragma unroll
        for (int i = 0; i < 4; i++) {
            float al = Arow[tr + 16 * i];
#pragma unroll
            for (int m = 0; m < 8; m++) O[i][m] *= al;
        }
#pragma unroll 4
        for (int j = 0; j < 64; j++) {
            float4 vA = *(const float4*)&Vs[j * 132 + cA];
            float4 vB = *(const float4*)&Vs[j * 132 + cB];
#pragma unroll
            for (int i = 0; i < 4; i++) {
                float p = KP[(tr + 16 * i) * 68 + j];
                O[i][0] += p * vA.x; O[i][1] += p * vA.y;
                O[i][2] += p * vA.z; O[i][3] += p * vA.w;
                O[i][4] += p * vB.x; O[i][5] += p * vB.y;
                O[i][6] += p * vB.z; O[i][7] += p * vB.w;
            }
        }
        __syncthreads();
    }

#pragma unroll
    for (int i = 0; i < 4; i++) {
        int rl = tr + 16 * i;
        float inv = 1.f / Lrow[rl];
        float4 oA = make_float4(O[i][0] * inv, O[i][1] * inv, O[i][2] * inv, O[i][3] * inv);
        float4 oB = make_float4(O[i][4] * inv, O[i][5] * inv, O[i][6] * inv, O[i][7] * inv);
        size_t base = (size_t)(tok0 + rl) * (NH * HD) + hq * HD;
        *(float4*)&o[base + cA] = oA;
        *(float4*)&o[base + cB] = oB;
    }
}

// ---------------- host orchestration ----------------
extern "C" void kernel_launch(void* const* d_in, const int* in_sizes, int n_in,
                              void* d_out, int out_size) {
    const float* x    = (const float*)d_in[0];
    const float* cosb = (const float*)d_in[2];
    const float* sinb = (const float*)d_in[3];
    const float* wq   = (const float*)d_in[4];
    const float* bq   = (const float*)d_in[5];
    const float* wk   = (const float*)d_in[6];
    const float* bk   = (const float*)d_in[7];
    const float* wv   = (const float*)d_in[8];
    const float* bv   = (const float*)d_in[9];
    const float* wo   = (const float*)d_in[10];
    const float* qnw  = (const float*)d_in[11];
    const float* knw  = (const float*)d_in[12];
    const float* ln1  = (const float*)d_in[13];
    const float* ln2  = (const float*)d_in[14];
    const float* wg   = (const float*)d_in[15];
    const float* wu   = (const float*)d_in[16];
    const float* wd   = (const float*)d_in[17];
    float* out = (float*)d_out;

    float *h_, *q_, *k_, *v_, *attn_, *x1_, *gate_;
    cudaGetSymbolAddress((void**)&h_,    g_h);
    cudaGetSymbolAddress((void**)&q_,    g_q);
    cudaGetSymbolAddress((void**)&k_,    g_k);
    cudaGetSymbolAddress((void**)&v_,    g_v);
    cudaGetSymbolAddress((void**)&attn_, g_attn);
    cudaGetSymbolAddress((void**)&x1_,   g_x1);
    cudaGetSymbolAddress((void**)&gate_, g_gate);

    const int attn_smem = ATTN_SMEM_FLOATS * 4;
    cudaFuncSetAttribute(attn_kernel, cudaFuncAttributeMaxDynamicSharedMemorySize, attn_smem);
    cudaFuncSetAttribute(gemm_std,  cudaFuncAttributeMaxDynamicSharedMemorySize, GEMM_SMEM_BYTES);
    cudaFuncSetAttribute(gemm_silu, cudaFuncAttributeMaxDynamicSharedMemorySize, GEMM_SMEM_BYTES);
    cudaFuncSetAttribute(gemm_qkv,  cudaFuncAttributeMaxDynamicSharedMemorySize, GEMM_SMEM_BYTES);

    // 1. h = RMSNorm(x, ln1)
    rmsnorm_kernel<<<TTOK, 256>>>(x, ln1, h_);
    // 2. fused q/k/v projections
    gemm_qkv<<<dim3(24, TTOK / 128), 256, GEMM_SMEM_BYTES>>>(h_, wq, bq, wk, bk, wv, bv, q_, k_, v_);
    // 3. per-head RMSNorm + RoPE
    qknorm_rope_kernel<<<dim3(TTOK, NH + NKV), 128>>>(q_, k_, qnw, knw, cosb, sinb);
    // 4. causal flash attention
    attn_kernel<<<dim3(SEQ / 64, NH, BATCH), 256, attn_smem>>>(q_, k_, v_, attn_);
    // 5. x1 = x + attn @ wo^T
    gemm_std<<<dim3(HIDN / 128, TTOK / 128), 256, GEMM_SMEM_BYTES>>>(attn_, wo, nullptr, x, x1_, HIDN, HIDN);
    // 6. h2 = RMSNorm(x1, ln2)
    rmsnorm_kernel<<<TTOK, 256>>>(x1_, ln2, h_);
    // 7. gate projection
    gemm_std<<<dim3(INTERN / 128, TTOK / 128), 256, GEMM_SMEM_BYTES>>>(h_, wg, nullptr, nullptr, gate_, INTERN, HIDN);
    // 8. up projection, fused: gate <- silu(gate) * up
    gemm_silu<<<dim3(INTERN / 128, TTOK / 128), 256, GEMM_SMEM_BYTES>>>(h_, wu, gate_, gate_, INTERN, HIDN);
    // 9. out = x1 + gate @ wd^T
    gemm_std<<<dim3(HIDN / 128, TTOK / 128), 256, GEMM_SMEM_BYTES>>>(gate_, wd, nullptr, x1_, out, HIDN, INTERN);
}

// round 6
// speedup vs baseline: 1.0539x; 1.0539x over previous
#include <cuda_runtime.h>
#include <cstdint>

#define HIDN   2048
#define NH     16
#define NKV    4
#define HD     128
#define INTERN 8192
#define BATCH  4
#define SEQ    1024
#define TTOK   (BATCH*SEQ)   /* 4096 */
#define EPSV   1e-6f
#define QK_SCALE 0.08838834764831845f  /* 1/sqrt(128) */

// ---------------- scratch ----------------
__device__ float g_h   [TTOK * HIDN];
__device__ float g_q   [TTOK * NH  * HD];
__device__ float g_k   [TTOK * NKV * HD];
__device__ float g_v   [TTOK * NKV * HD];
__device__ float g_attn[TTOK * HIDN];
__device__ float g_x1  [TTOK * HIDN];
__device__ float g_gate[TTOK * INTERN];

// ---------------- tf32 mma helpers ----------------
__device__ __forceinline__ uint32_t f2tf(float f) {
    uint32_t u; asm("cvt.rna.tf32.f32 %0, %1;" : "=r"(u) : "f"(f)); return u;
}
__device__ __forceinline__ uint4 f2tf4(float4 v) {
    uint4 u;
    u.x = f2tf(v.x); u.y = f2tf(v.y); u.z = f2tf(v.z); u.w = f2tf(v.w);
    return u;
}
__device__ __forceinline__ void mma_tf32(float c[4], const uint32_t a[4], const uint32_t b[2]) {
    asm volatile("mma.sync.aligned.m16n8k8.row.col.f32.tf32.tf32.f32 "
        "{%0,%1,%2,%3}, {%4,%5,%6,%7}, {%8,%9}, {%0,%1,%2,%3};\n"
        : "+f"(c[0]), "+f"(c[1]), "+f"(c[2]), "+f"(c[3])
        : "r"(a[0]), "r"(a[1]), "r"(a[2]), "r"(a[3]), "r"(b[0]), "r"(b[1]));
}

// ---------------- GEMM (round-2 measured-best config: two syncs per k-tile) ----------------
// BM=128, BN=128, BK=32; 256 thr = 8 warps (2M x 4N), warp tile 64x32.
// MODE 0: C = acc (+bias)(+res).  MODE 1: C = silu(res)*acc.
#define GSTRIDE 36
#define GBUF    (128 * GSTRIDE)
#define GEMM_SMEM_BYTES (4 * GBUF * 4)

template<int MODE>
__device__ __forceinline__ void gemm_body(
    const float* __restrict__ A, const float* __restrict__ B,
    const float* __restrict__ bias, const float* __restrict__ res,
    float* __restrict__ C, int ldc, int K, int brow, int bcol)
{
    extern __shared__ uint32_t smem[];
    uint32_t* As = smem;
    uint32_t* Bs = smem + 2 * GBUF;

    const int tid  = threadIdx.x;
    const int lane = tid & 31, warp = tid >> 5;
    const int wm = warp & 1, wn = warp >> 1;
    const int g  = lane >> 2, t4 = lane & 3;

    const int lr = tid >> 3;
    const int lc = (tid & 7) << 2;
    const float* aptr = A + (size_t)(brow + lr) * K + lc;
    const float* bptr = B + (size_t)(bcol + lr) * K + lc;
    const int soff = lr * GSTRIDE + lc;

    float acc[4][4][4];
#pragma unroll
    for (int i = 0; i < 4; i++)
#pragma unroll
        for (int j = 0; j < 4; j++)
#pragma unroll
            for (int e = 0; e < 4; e++) acc[i][j][e] = 0.f;

    float4 ra[4], rb[4];
#pragma unroll
    for (int r = 0; r < 4; r++) {
        ra[r] = *(const float4*)(aptr + (size_t)(r * 32) * K);
        rb[r] = *(const float4*)(bptr + (size_t)(r * 32) * K);
    }
#pragma unroll
    for (int r = 0; r < 4; r++) {
        *(uint4*)&As[soff + r * 32 * GSTRIDE] = f2tf4(ra[r]);
        *(uint4*)&Bs[soff + r * 32 * GSTRIDE] = f2tf4(rb[r]);
    }
    __syncthreads();

    const int nk = K >> 5;
    for (int t = 0; t < nk; ++t) {
        const int cur = t & 1;
        if (t + 1 < nk) {
            const float* ap = aptr + (size_t)(t + 1) * 32;
            const float* bp = bptr + (size_t)(t + 1) * 32;
#pragma unroll
            for (int r = 0; r < 4; r++) {
                ra[r] = *(const float4*)(ap + (size_t)(r * 32) * K);
                rb[r] = *(const float4*)(bp + (size_t)(r * 32) * K);
            }
        }
        const uint32_t* As_ = As + cur * GBUF;
        const uint32_t* Bs_ = Bs + cur * GBUF;
#pragma unroll
        for (int kb = 0; kb < 32; kb += 8) {
            uint32_t af[4][4], bf[4][2];
#pragma unroll
            for (int mt = 0; mt < 4; ++mt) {
                int base = (wm * 64 + mt * 16 + g) * GSTRIDE + kb + t4;
                af[mt][0] = As_[base];
                af[mt][1] = As_[base + 8 * GSTRIDE];
                af[mt][2] = As_[base + 4];
                af[mt][3] = As_[base + 8 * GSTRIDE + 4];
            }
#pragma unroll
            for (int nt = 0; nt < 4; ++nt) {
                int nbase = (wn * 32 + nt * 8 + g) * GSTRIDE + kb + t4;
                bf[nt][0] = Bs_[nbase];
                bf[nt][1] = Bs_[nbase + 4];
            }
#pragma unroll
            for (int mt = 0; mt < 4; ++mt)
#pragma unroll
                for (int nt = 0; nt < 4; ++nt)
                    mma_tf32(acc[mt][nt], af[mt], bf[nt]);
        }
        __syncthreads();
        if (t + 1 < nk) {
            uint32_t* An = As + (cur ^ 1) * GBUF;
            uint32_t* Bn = Bs + (cur ^ 1) * GBUF;
#pragma unroll
            for (int r = 0; r < 4; r++) {
                *(uint4*)&An[soff + r * 32 * GSTRIDE] = f2tf4(ra[r]);
                *(uint4*)&Bn[soff + r * 32 * GSTRIDE] = f2tf4(rb[r]);
            }
            __syncthreads();
        }
    }

#pragma unroll
    for (int mt = 0; mt < 4; ++mt) {
        int r0 = brow + wm * 64 + mt * 16 + g;
#pragma unroll
        for (int nt = 0; nt < 4; ++nt) {
            int c0 = bcol + wn * 32 + nt * 8 + t4 * 2;
            float2 v0 = make_float2(acc[mt][nt][0], acc[mt][nt][1]);
            float2 v1 = make_float2(acc[mt][nt][2], acc[mt][nt][3]);
            if (MODE == 1) {
                float2 ga = *(const float2*)&res[(size_t)r0 * ldc + c0];
                float2 gb = *(const float2*)&res[(size_t)(r0 + 8) * ldc + c0];
                v0.x *= ga.x / (1.f + __expf(-ga.x));
                v0.y *= ga.y / (1.f + __expf(-ga.y));
                v1.x *= gb.x / (1.f + __expf(-gb.x));
                v1.y *= gb.y / (1.f + __expf(-gb.y));
            } else {
                if (bias) {
                    float2 bv = *(const float2*)&bias[c0];
                    v0.x += bv.x; v0.y += bv.y; v1.x += bv.x; v1.y += bv.y;
                }
                if (res) {
                    float2 rra = *(const float2*)&res[(size_t)r0 * ldc + c0];
                    float2 rrb = *(const float2*)&res[(size_t)(r0 + 8) * ldc + c0];
                    v0.x += rra.x; v0.y += rra.y; v1.x += rrb.x; v1.y += rrb.y;
                }
            }
            *(float2*)&C[(size_t)r0 * ldc + c0]       = v0;
            *(float2*)&C[(size_t)(r0 + 8) * ldc + c0] = v1;
        }
    }
}

__global__ __launch_bounds__(256)
void gemm_std(const float* __restrict__ A, const float* __restrict__ B,
              const float* __restrict__ bias, const float* __restrict__ res,
              float* __restrict__ C, int ldc, int K) {
    gemm_body<0>(A, B, bias, res, C, ldc, K, blockIdx.y << 7, blockIdx.x << 7);
}

__global__ __launch_bounds__(256)
void gemm_silu(const float* __restrict__ A, const float* __restrict__ B,
               const float* __restrict__ gate, float* __restrict__ C, int ldc, int K) {
    gemm_body<1>(A, B, nullptr, gate, C, ldc, K, blockIdx.y << 7, blockIdx.x << 7);
}

// ---------------- RMSNorm over HIDN=2048 ----------------
__global__ void rmsnorm_kernel(const float* __restrict__ x, const float* __restrict__ w,
                               float* __restrict__ out) {
    int row = blockIdx.x;
    const float* xr = x + (size_t)row * HIDN;
    float4 v[2];
    float ss = 0.f;
#pragma unroll
    for (int i = 0; i < 2; i++) {
        v[i] = *(const float4*)&xr[(threadIdx.x + i * 256) * 4];
        ss += v[i].x * v[i].x + v[i].y * v[i].y + v[i].z * v[i].z + v[i].w * v[i].w;
    }
#pragma unroll
    for (int o = 16; o; o >>= 1) ss += __shfl_xor_sync(~0u, ss, o);
    __shared__ float red[8];
    if ((threadIdx.x & 31) == 0) red[threadIdx.x >> 5] = ss;
    __syncthreads();
    if (threadIdx.x == 0) {
        float t = 0.f;
#pragma unroll
        for (int i = 0; i < 8; i++) t += red[i];
        red[0] = rsqrtf(t / (float)HIDN + EPSV);
    }
    __syncthreads();
    float r = red[0];
#pragma unroll
    for (int i = 0; i < 2; i++) {
        int c = (threadIdx.x + i * 256) * 4;
        float4 wv = *(const float4*)&w[c];
        float4 o4 = make_float4(v[i].x * r * wv.x, v[i].y * r * wv.y,
                                v[i].z * r * wv.z, v[i].w * r * wv.w);
        *(float4*)&out[(size_t)row * HIDN + c] = o4;
    }
}

// ---------------- per-head RMSNorm + RoPE ----------------
__global__ void qknorm_rope_kernel(float* __restrict__ qb, float* __restrict__ kb,
                                   const float* __restrict__ qw, const float* __restrict__ kw,
                                   const float* __restrict__ cs, const float* __restrict__ sn) {
    int token = blockIdx.x, h = blockIdx.y;
    float* p; const float* w;
    if (h < NH) { p = qb + (size_t)token * (NH * HD)  + h * HD;        w = qw; }
    else        { p = kb + (size_t)token * (NKV * HD) + (h - NH) * HD; w = kw; }
    int d = threadIdx.x;
    float v = p[d];
    float ss = v * v;
#pragma unroll
    for (int o = 16; o; o >>= 1) ss += __shfl_xor_sync(~0u, ss, o);
    __shared__ float red[4];
    __shared__ float sh[128];
    if ((d & 31) == 0) red[d >> 5] = ss;
    __syncthreads();
    float tot = red[0] + red[1] + red[2] + red[3];
    float r = rsqrtf(tot / 128.f + EPSV);
    float xn = v * r * w[d];
    sh[d] = xn;
    __syncthreads();
    float rot = (d < 64) ? -sh[d + 64] : sh[d - 64];
    float c = cs[(size_t)token * 128 + d], s = sn[(size_t)token * 128 + d];
    p[d] = xn * c + rot * s;
}

// ---------------- flash attention (tf32 MMA, causal, GQA) ----------------
// Tile 64(q) x 64(k), HD=128. 256 thr = 8 warps: 4(M, 16 rows each) x 2(N).
// S phase: warp n-extent 32 cols; PV phase: warp n-extent 64 d-cols.
// smem strides chosen for conflict-free fragment LDS:
//   row-major A / [n][k] B operands: stride % 32 == 4  -> 132 (Q,K), 68 (P)
//   V as [k][d] B operand:           stride % 32 == 8  -> 136
#define AQ_STRIDE 132
#define AV_STRIDE 136
#define AP_STRIDE 68
#define ATTN_U32  (2 * 64 * AQ_STRIDE + 64 * AV_STRIDE + 64 * AP_STRIDE + 2*64 + 2*64 + 3*64)
#define ATTN_SMEM_BYTES (ATTN_U32 * 4)

__global__ __launch_bounds__(256)
void attn_kernel(const float* __restrict__ q, const float* __restrict__ k,
                 const float* __restrict__ v, float* __restrict__ o) {
    extern __shared__ uint32_t smem[];
    uint32_t* Qs = smem;
    uint32_t* Ks = Qs + 64 * AQ_STRIDE;
    uint32_t* Vs = Ks + 64 * AQ_STRIDE;
    uint32_t* Ps = Vs + 64 * AV_STRIDE;
    float* Pmax = (float*)(Ps + 64 * AP_STRIDE);  // [2][64] per-warp-col partial max
    float* Psum = Pmax + 128;                     // [2][64] partial sums
    float* Mrow = Psum + 128;
    float* Lrow = Mrow + 64;
    float* Arow = Lrow + 64;

    const int tid  = threadIdx.x;
    const int lane = tid & 31, warp = tid >> 5;
    const int wm = warp & 3, wn = warp >> 2;     // 4 x 2
    const int g = lane >> 2, t4 = lane & 3;
    const int qt = blockIdx.x, hq = blockIdx.y, b = blockIdx.z;
    const int kvh = hq >> 2;
    const int tok0 = b * SEQ + qt * 64;

    const int r0 = wm * 16 + g, r1 = r0 + 8;

    // load Q tile (scaled, tf32)
    for (int l = tid; l < 64 * 32; l += 256) {
        int r = l >> 5, d4 = (l & 31) * 4;
        float4 qv = *(const float4*)&q[(size_t)(tok0 + r) * (NH * HD) + hq * HD + d4];
        qv.x *= QK_SCALE; qv.y *= QK_SCALE; qv.z *= QK_SCALE; qv.w *= QK_SCALE;
        *(uint4*)&Qs[r * AQ_STRIDE + d4] = f2tf4(qv);
    }
    if (tid < 64) { Mrow[tid] = -3.0e38f; Lrow[tid] = 0.f; }

    float O[8][4];
#pragma unroll
    for (int nt = 0; nt < 8; nt++)
#pragma unroll
        for (int e = 0; e < 4; e++) O[nt][e] = 0.f;
    __syncthreads();

    for (int kt = 0; kt <= qt; ++kt) {
        // load K, V tiles (tf32)
        for (int l = tid; l < 64 * 32; l += 256) {
            int r = l >> 5, d4 = (l & 31) * 4;
            size_t base = (size_t)(b * SEQ + kt * 64 + r) * (NKV * HD) + kvh * HD + d4;
            *(uint4*)&Ks[r * AQ_STRIDE + d4] = f2tf4(*(const float4*)&k[base]);
            *(uint4*)&Vs[r * AV_STRIDE + d4] = f2tf4(*(const float4*)&v[base]);
        }
        __syncthreads();

        // ---- S = Q K^T (warp tile 16 x 32) ----
        float s[4][4];
#pragma unroll
        for (int nt = 0; nt < 4; nt++)
#pragma unroll
            for (int e = 0; e < 4; e++) s[nt][e] = 0.f;
        {
            const int arow0 = r0 * AQ_STRIDE, arow1 = r1 * AQ_STRIDE;
#pragma unroll
            for (int kb = 0; kb < 128; kb += 8) {
                uint32_t a[4];
                a[0] = Qs[arow0 + kb + t4];
                a[1] = Qs[arow1 + kb + t4];
                a[2] = Qs[arow0 + kb + t4 + 4];
                a[3] = Qs[arow1 + kb + t4 + 4];
#pragma unroll
                for (int nt = 0; nt < 4; nt++) {
                    uint32_t bb[2];
                    int nb = (wn * 32 + nt * 8 + g) * AQ_STRIDE + kb + t4;
                    bb[0] = Ks[nb]; bb[1] = Ks[nb + 4];
                    mma_tf32(s[nt], a, bb);
                }
            }
        }

        // causal mask (diag tile only)
        if (kt == qt) {
#pragma unroll
            for (int nt = 0; nt < 4; nt++) {
                int c0 = wn * 32 + nt * 8 + 2 * t4;
                if (c0     > r0) s[nt][0] = -1.0e30f;
                if (c0 + 1 > r0) s[nt][1] = -1.0e30f;
                if (c0     > r1) s[nt][2] = -1.0e30f;
                if (c0 + 1 > r1) s[nt][3] = -1.0e30f;
            }
        }

        // warp-partial row max over 32 cols
        {
            float mx0 = fmaxf(fmaxf(s[0][0], s[0][1]), fmaxf(s[1][0], s[1][1]));
            mx0 = fmaxf(mx0, fmaxf(fmaxf(s[2][0], s[2][1]), fmaxf(s[3][0], s[3][1])));
            float mx1 = fmaxf(fmaxf(s[0][2], s[0][3]), fmaxf(s[1][2], s[1][3]));
            mx1 = fmaxf(mx1, fmaxf(fmaxf(s[2][2], s[2][3]), fmaxf(s[3][2], s[3][3])));
            mx0 = fmaxf(mx0, __shfl_xor_sync(~0u, mx0, 1));
            mx0 = fmaxf(mx0, __shfl_xor_sync(~0u, mx0, 2));
            mx1 = fmaxf(mx1, __shfl_xor_sync(~0u, mx1, 1));
            mx1 = fmaxf(mx1, __shfl_xor_sync(~0u, mx1, 2));
            if (t4 == 0) { Pmax[wn * 64 + r0] = mx0; Pmax[wn * 64 + r1] = mx1; }
        }
        __syncthreads();

        // p = exp(s - mnew); write tf32 P tile; partial row sums
        {
            float mn0 = fmaxf(Mrow[r0], fmaxf(Pmax[r0], Pmax[64 + r0]));
            float mn1 = fmaxf(Mrow[r1], fmaxf(Pmax[r1], Pmax[64 + r1]));
            float sum0 = 0.f, sum1 = 0.f;
#pragma unroll
            for (int nt = 0; nt < 4; nt++) {
                int c = wn * 32 + nt * 8 + 2 * t4;
                float p0 = __expf(s[nt][0] - mn0);
                float p1 = __expf(s[nt][1] - mn0);
                float p2 = __expf(s[nt][2] - mn1);
                float p3 = __expf(s[nt][3] - mn1);
                sum0 += p0 + p1; sum1 += p2 + p3;
                *(uint2*)&Ps[r0 * AP_STRIDE + c] = make_uint2(f2tf(p0), f2tf(p1));
                *(uint2*)&Ps[r1 * AP_STRIDE + c] = make_uint2(f2tf(p2), f2tf(p3));
            }
            sum0 += __shfl_xor_sync(~0u, sum0, 1);
            sum0 += __shfl_xor_sync(~0u, sum0, 2);
            sum1 += __shfl_xor_sync(~0u, sum1, 1);
            sum1 += __shfl_xor_sync(~0u, sum1, 2);
            if (t4 == 0) { Psum[wn * 64 + r0] = sum0; Psum[wn * 64 + r1] = sum1; }
        }
        __syncthreads();

        // update running stats
        if (tid < 64) {
            int r = tid;
            float mo = Mrow[r];
            float mn = fmaxf(mo, fmaxf(Pmax[r], Pmax[64 + r]));
            float al = __expf(mo - mn);
            Lrow[r] = Lrow[r] * al + Psum[r] + Psum[64 + r];
            Mrow[r] = mn;
            Arow[r] = al;
        }
        __syncthreads();

        // rescale O, then O += P V  (warp tile 16 x 64)
        {
            float al0 = Arow[r0], al1 = Arow[r1];
#pragma unroll
            for (int nt = 0; nt < 8; nt++) {
                O[nt][0] *= al0; O[nt][1] *= al0;
                O[nt][2] *= al1; O[nt][3] *= al1;
            }
            const int prow0 = r0 * AP_STRIDE, prow1 = r1 * AP_STRIDE;
#pragma unroll
            for (int kb = 0; kb < 64; kb += 8) {
                uint32_t a[4];
                a[0] = Ps[prow0 + kb + t4];
                a[1] = Ps[prow1 + kb + t4];
                a[2] = Ps[prow0 + kb + t4 + 4];
                a[3] = Ps[prow1 + kb + t4 + 4];
#pragma unroll
                for (int nt = 0; nt < 8; nt++) {
                    uint32_t bb[2];
                    int col = wn * 64 + nt * 8 + g;
                    bb[0] = Vs[(kb + t4) * AV_STRIDE + col];
                    bb[1] = Vs[(kb + t4 + 4) * AV_STRIDE + col];
                    mma_tf32(O[nt], a, bb);
                }
            }
        }
        __syncthreads();   // protect Ks/Vs/Ps before next tile load
    }

    // epilogue: normalize by L, write out
    {
        float inv0 = 1.f / Lrow[r0], inv1 = 1.f / Lrow[r1];
        size_t base0 = (size_t)(tok0 + r0) * (NH * HD) + hq * HD;
        size_t base1 = (size_t)(tok0 + r1) * (NH * HD) + hq * HD;
#pragma unroll
        for (int nt = 0; nt < 8; nt++) {
            int c = wn * 64 + nt * 8 + 2 * t4;
            *(float2*)&o[base0 + c] = make_float2(O[nt][0] * inv0, O[nt][1] * inv0);
            *(float2*)&o[base1 + c] = make_float2(O[nt][2] * inv1, O[nt][3] * inv1);
        }
    }
}

// ---------------- host orchestration ----------------
extern "C" void kernel_launch(void* const* d_in, const int* in_sizes, int n_in,
                              void* d_out, int out_size) {
    const float* x    = (const float*)d_in[0];
    const float* cosb = (const float*)d_in[2];
    const float* sinb = (const float*)d_in[3];
    const float* wq   = (const float*)d_in[4];
    const float* bq   = (const float*)d_in[5];
    const float* wk   = (const float*)d_in[6];
    const float* bk   = (const float*)d_in[7];
    const float* wv   = (const float*)d_in[8];
    const float* bv   = (const float*)d_in[9];
    const float* wo   = (const float*)d_in[10];
    const float* qnw  = (const float*)d_in[11];
    const float* knw  = (const float*)d_in[12];
    const float* ln1  = (const float*)d_in[13];
    const float* ln2  = (const float*)d_in[14];
    const float* wg   = (const float*)d_in[15];
    const float* wu   = (const float*)d_in[16];
    const float* wd   = (const float*)d_in[17];
    float* out = (float*)d_out;

    float *h_, *q_, *k_, *v_, *attn_, *x1_, *gate_;
    cudaGetSymbolAddress((void**)&h_,    g_h);
    cudaGetSymbolAddress((void**)&q_,    g_q);
    cudaGetSymbolAddress((void**)&k_,    g_k);
    cudaGetSymbolAddress((void**)&v_,    g_v);
    cudaGetSymbolAddress((void**)&attn_, g_attn);
    cudaGetSymbolAddress((void**)&x1_,   g_x1);
    cudaGetSymbolAddress((void**)&gate_, g_gate);

    cudaFuncSetAttribute(attn_kernel, cudaFuncAttributeMaxDynamicSharedMemorySize, ATTN_SMEM_BYTES);
    cudaFuncSetAttribute(gemm_std,  cudaFuncAttributeMaxDynamicSharedMemorySize, GEMM_SMEM_BYTES);
    cudaFuncSetAttribute(gemm_silu, cudaFuncAttributeMaxDynamicSharedMemorySize, GEMM_SMEM_BYTES);

    // 1. h = RMSNorm(x, ln1)
    rmsnorm_kernel<<<TTOK, 256>>>(x, ln1, h_);
    // 2-4. q/k/v projections
    gemm_std<<<dim3(HIDN / 128, TTOK / 128), 256, GEMM_SMEM_BYTES>>>(h_, wq, bq, nullptr, q_, NH * HD, HIDN);
    gemm_std<<<dim3((NKV * HD) / 128, TTOK / 128), 256, GEMM_SMEM_BYTES>>>(h_, wk, bk, nullptr, k_, NKV * HD, HIDN);
    gemm_std<<<dim3((NKV * HD) / 128, TTOK / 128), 256, GEMM_SMEM_BYTES>>>(h_, wv, bv, nullptr, v_, NKV * HD, HIDN);
    // 5. per-head RMSNorm + RoPE
    qknorm_rope_kernel<<<dim3(TTOK, NH + NKV), 128>>>(q_, k_, qnw, knw, cosb, sinb);
    // 6. causal flash attention (tf32 MMA)
    attn_kernel<<<dim3(SEQ / 64, NH, BATCH), 256, ATTN_SMEM_BYTES>>>(q_, k_, v_, attn_);
    // 7. x1 = x + attn @ wo^T
    gemm_std<<<dim3(HIDN / 128, TTOK / 128), 256, GEMM_SMEM_BYTES>>>(attn_, wo, nullptr, x, x1_, HIDN, HIDN);
    // 8. h2 = RMSNorm(x1, ln2)
    rmsnorm_kernel<<<TTOK, 256>>>(x1_, ln2, h_);
    // 9. gate projection
    gemm_std<<<dim3(INTERN / 128, TTOK / 128), 256, GEMM_SMEM_BYTES>>>(h_, wg, nullptr, nullptr, gate_, INTERN, HIDN);
    // 10. up projection, fused: gate <- silu(gate) * up
    gemm_silu<<<dim3(INTERN / 128, TTOK / 128), 256, GEMM_SMEM_BYTES>>>(h_, wu, gate_, gate_, INTERN, HIDN);
    // 11. out = x1 + gate @ wd^T
    gemm_std<<<dim3(HIDN / 128, TTOK / 128), 256, GEMM_SMEM_BYTES>>>(gate_, wd, nullptr, x1_, out, HIDN, INTERN);
}

// round 7
// speedup vs baseline: 1.4000x; 1.3284x over previous
#include <cuda_runtime.h>
#include <cuda_fp16.h>
#include <cstdint>

#define HIDN   2048
#define NH     16
#define NKV    4
#define HD     128
#define INTERN 8192
#define BATCH  4
#define SEQ    1024
#define TTOK   (BATCH*SEQ)   /* 4096 */
#define EPSV   1e-6f
#define QK_SCALE 0.08838834764831845f  /* 1/sqrt(128) */

// ---------------- scratch ----------------
__device__ float g_h   [TTOK * HIDN];
__device__ float g_q   [TTOK * NH  * HD];
__device__ float g_k   [TTOK * NKV * HD];
__device__ float g_v   [TTOK * NKV * HD];
__device__ float g_attn[TTOK * HIDN];
__device__ float g_x1  [TTOK * HIDN];
__device__ float g_gate[TTOK * INTERN];

// ---------------- mma helpers ----------------
__device__ __forceinline__ uint32_t f2tf(float f) {
    uint32_t u; asm("cvt.rna.tf32.f32 %0, %1;" : "=r"(u) : "f"(f)); return u;
}
__device__ __forceinline__ uint4 f2tf4(float4 v) {
    uint4 u;
    u.x = f2tf(v.x); u.y = f2tf(v.y); u.z = f2tf(v.z); u.w = f2tf(v.w);
    return u;
}
__device__ __forceinline__ void mma_tf32(float c[4], const uint32_t a[4], const uint32_t b[2]) {
    asm volatile("mma.sync.aligned.m16n8k8.row.col.f32.tf32.tf32.f32 "
        "{%0,%1,%2,%3}, {%4,%5,%6,%7}, {%8,%9}, {%0,%1,%2,%3};\n"
        : "+f"(c[0]), "+f"(c[1]), "+f"(c[2]), "+f"(c[3])
        : "r"(a[0]), "r"(a[1]), "r"(a[2]), "r"(a[3]), "r"(b[0]), "r"(b[1]));
}
// fp16 m16n8k16, fp32 accumulate
__device__ __forceinline__ void mma_f16(float c[4], const uint32_t a[4], const uint32_t b[2]) {
    asm volatile("mma.sync.aligned.m16n8k16.row.col.f32.f16.f16.f32 "
        "{%0,%1,%2,%3}, {%4,%5,%6,%7}, {%8,%9}, {%0,%1,%2,%3};\n"
        : "+f"(c[0]), "+f"(c[1]), "+f"(c[2]), "+f"(c[3])
        : "r"(a[0]), "r"(a[1]), "r"(a[2]), "r"(a[3]), "r"(b[0]), "r"(b[1]));
}
__device__ __forceinline__ uint32_t pack_h2(float lo, float hi) {
    __half2 h = __floats2half2_rn(lo, hi);   // lo -> .x (low half)
    return *(uint32_t*)&h;
}
__device__ __forceinline__ uint2 f2h4(float4 v) {
    return make_uint2(pack_h2(v.x, v.y), pack_h2(v.z, v.w));
}

// ---------------- fp16 GEMM: C[.,ldc] = A[M,K] @ B[N,K]^T + epilogue ----------------
// BM=128, BN=128, BK=32; 256 thr = 8 warps (2M x 4N), warp tile 64x32.
// smem: half2-packed u32 words, row = 16 data u32 + 4 pad (stride 20, conflict-free).
// Two syncthreads per k-tile (measured-best double-buffer discipline).
// MODE 0: C = acc (+bias)(+res).  MODE 1: C = silu(res)*acc.
#define GSTRIDE 20
#define GBUF    (128 * GSTRIDE)
#define GEMM_SMEM_BYTES (4 * GBUF * 4)   /* 40 KB */

template<int MODE>
__device__ __forceinline__ void gemm_body(
    const float* __restrict__ A, const float* __restrict__ B,
    const float* __restrict__ bias, const float* __restrict__ res,
    float* __restrict__ C, int ldc, int K, int brow, int bcol)
{
    extern __shared__ uint32_t smem[];
    uint32_t* As = smem;
    uint32_t* Bs = smem + 2 * GBUF;

    const int tid  = threadIdx.x;
    const int lane = tid & 31, warp = tid >> 5;
    const int wm = warp & 1, wn = warp >> 1;
    const int g  = lane >> 2, t4 = lane & 3;

    const int lr = tid >> 3;             // 0..31  (rows lr, +32, +64, +96)
    const int lcf = (tid & 7) << 2;      // float col 0,4,...,28
    const float* aptr = A + (size_t)(brow + lr) * K + lcf;
    const float* bptr = B + (size_t)(bcol + lr) * K + lcf;
    const int soff = lr * GSTRIDE + ((tid & 7) << 1);  // u32 offset

    float acc[4][4][4];
#pragma unroll
    for (int i = 0; i < 4; i++)
#pragma unroll
        for (int j = 0; j < 4; j++)
#pragma unroll
            for (int e = 0; e < 4; e++) acc[i][j][e] = 0.f;

    float4 ra[4], rb[4];
#pragma unroll
    for (int r = 0; r < 4; r++) {
        ra[r] = *(const float4*)(aptr + (size_t)(r * 32) * K);
        rb[r] = *(const float4*)(bptr + (size_t)(r * 32) * K);
    }
#pragma unroll
    for (int r = 0; r < 4; r++) {
        *(uint2*)&As[soff + r * 32 * GSTRIDE] = f2h4(ra[r]);
        *(uint2*)&Bs[soff + r * 32 * GSTRIDE] = f2h4(rb[r]);
    }
    __syncthreads();

    const int nk = K >> 5;
    for (int t = 0; t < nk; ++t) {
        const int cur = t & 1;
        if (t + 1 < nk) {
            const float* ap = aptr + (size_t)(t + 1) * 32;
            const float* bp = bptr + (size_t)(t + 1) * 32;
#pragma unroll
            for (int r = 0; r < 4; r++) {
                ra[r] = *(const float4*)(ap + (size_t)(r * 32) * K);
                rb[r] = *(const float4*)(bp + (size_t)(r * 32) * K);
            }
        }
        const uint32_t* As_ = As + cur * GBUF;
        const uint32_t* Bs_ = Bs + cur * GBUF;
        // BK=32 halves = 2 k-chunks of 16 (8 u32 each)
#pragma unroll
        for (int kb = 0; kb < 16; kb += 8) {
            uint32_t af[4][4], bf[4][2];
#pragma unroll
            for (int mt = 0; mt < 4; ++mt) {
                int base = (wm * 64 + mt * 16 + g) * GSTRIDE + kb + t4;
                af[mt][0] = As_[base];
                af[mt][1] = As_[base + 8 * GSTRIDE];
                af[mt][2] = As_[base + 4];
                af[mt][3] = As_[base + 8 * GSTRIDE + 4];
            }
#pragma unroll
            for (int nt = 0; nt < 4; ++nt) {
                int nbase = (wn * 32 + nt * 8 + g) * GSTRIDE + kb + t4;
                bf[nt][0] = Bs_[nbase];
                bf[nt][1] = Bs_[nbase + 4];
            }
#pragma unroll
            for (int mt = 0; mt < 4; ++mt)
#pragma unroll
                for (int nt = 0; nt < 4; ++nt)
                    mma_f16(acc[mt][nt], af[mt], bf[nt]);
        }
        __syncthreads();
        if (t + 1 < nk) {
            uint32_t* An = As + (cur ^ 1) * GBUF;
            uint32_t* Bn = Bs + (cur ^ 1) * GBUF;
#pragma unroll
            for (int r = 0; r < 4; r++) {
                *(uint2*)&An[soff + r * 32 * GSTRIDE] = f2h4(ra[r]);
                *(uint2*)&Bn[soff + r * 32 * GSTRIDE] = f2h4(rb[r]);
            }
            __syncthreads();
        }
    }

#pragma unroll
    for (int mt = 0; mt < 4; ++mt) {
        int r0 = brow + wm * 64 + mt * 16 + g;
#pragma unroll
        for (int nt = 0; nt < 4; ++nt) {
            int c0 = bcol + wn * 32 + nt * 8 + t4 * 2;
            float2 v0 = make_float2(acc[mt][nt][0], acc[mt][nt][1]);
            float2 v1 = make_float2(acc[mt][nt][2], acc[mt][nt][3]);
            if (MODE == 1) {
                float2 ga = *(const float2*)&res[(size_t)r0 * ldc + c0];
                float2 gb = *(const float2*)&res[(size_t)(r0 + 8) * ldc + c0];
                v0.x *= ga.x / (1.f + __expf(-ga.x));
                v0.y *= ga.y / (1.f + __expf(-ga.y));
                v1.x *= gb.x / (1.f + __expf(-gb.x));
                v1.y *= gb.y / (1.f + __expf(-gb.y));
            } else {
                if (bias) {
                    float2 bv = *(const float2*)&bias[c0];
                    v0.x += bv.x; v0.y += bv.y; v1.x += bv.x; v1.y += bv.y;
                }
                if (res) {
                    float2 rra = *(const float2*)&res[(size_t)r0 * ldc + c0];
                    float2 rrb = *(const float2*)&res[(size_t)(r0 + 8) * ldc + c0];
                    v0.x += rra.x; v0.y += rra.y; v1.x += rrb.x; v1.y += rrb.y;
                }
            }
            *(float2*)&C[(size_t)r0 * ldc + c0]       = v0;
            *(float2*)&C[(size_t)(r0 + 8) * ldc + c0] = v1;
        }
    }
}

__global__ __launch_bounds__(256)
void gemm_std(const float* __restrict__ A, const float* __restrict__ B,
              const float* __restrict__ bias, const float* __restrict__ res,
              float* __restrict__ C, int ldc, int K) {
    gemm_body<0>(A, B, bias, res, C, ldc, K, blockIdx.y << 7, blockIdx.x << 7);
}

__global__ __launch_bounds__(256)
void gemm_silu(const float* __restrict__ A, const float* __restrict__ B,
               const float* __restrict__ gate, float* __restrict__ C, int ldc, int K) {
    gemm_body<1>(A, B, nullptr, gate, C, ldc, K, blockIdx.y << 7, blockIdx.x << 7);
}

// ---------------- RMSNorm over HIDN=2048 ----------------
__global__ void rmsnorm_kernel(const float* __restrict__ x, const float* __restrict__ w,
                               float* __restrict__ out) {
    int row = blockIdx.x;
    const float* xr = x + (size_t)row * HIDN;
    float4 v[2];
    float ss = 0.f;
#pragma unroll
    for (int i = 0; i < 2; i++) {
        v[i] = *(const float4*)&xr[(threadIdx.x + i * 256) * 4];
        ss += v[i].x * v[i].x + v[i].y * v[i].y + v[i].z * v[i].z + v[i].w * v[i].w;
    }
#pragma unroll
    for (int o = 16; o; o >>= 1) ss += __shfl_xor_sync(~0u, ss, o);
    __shared__ float red[8];
    if ((threadIdx.x & 31) == 0) red[threadIdx.x >> 5] = ss;
    __syncthreads();
    if (threadIdx.x == 0) {
        float t = 0.f;
#pragma unroll
        for (int i = 0; i < 8; i++) t += red[i];
        red[0] = rsqrtf(t / (float)HIDN + EPSV);
    }
    __syncthreads();
    float r = red[0];
#pragma unroll
    for (int i = 0; i < 2; i++) {
        int c = (threadIdx.x + i * 256) * 4;
        float4 wv = *(const float4*)&w[c];
        float4 o4 = make_float4(v[i].x * r * wv.x, v[i].y * r * wv.y,
                                v[i].z * r * wv.z, v[i].w * r * wv.w);
        *(float4*)&out[(size_t)row * HIDN + c] = o4;
    }
}

// ---------------- per-head RMSNorm + RoPE ----------------
__global__ void qknorm_rope_kernel(float* __restrict__ qb, float* __restrict__ kb,
                                   const float* __restrict__ qw, const float* __restrict__ kw,
                                   const float* __restrict__ cs, const float* __restrict__ sn) {
    int token = blockIdx.x, h = blockIdx.y;
    float* p; const float* w;
    if (h < NH) { p = qb + (size_t)token * (NH * HD)  + h * HD;        w = qw; }
    else        { p = kb + (size_t)token * (NKV * HD) + (h - NH) * HD; w = kw; }
    int d = threadIdx.x;
    float v = p[d];
    float ss = v * v;
#pragma unroll
    for (int o = 16; o; o >>= 1) ss += __shfl_xor_sync(~0u, ss, o);
    __shared__ float red[4];
    __shared__ float sh[128];
    if ((d & 31) == 0) red[d >> 5] = ss;
    __syncthreads();
    float tot = red[0] + red[1] + red[2] + red[3];
    float r = rsqrtf(tot / 128.f + EPSV);
    float xn = v * r * w[d];
    sh[d] = xn;
    __syncthreads();
    float rot = (d < 64) ? -sh[d + 64] : sh[d - 64];
    float c = cs[(size_t)token * 128 + d], s = sn[(size_t)token * 128 + d];
    p[d] = xn * c + rot * s;
}

// ---------------- flash attention (tf32 MMA, causal, GQA) ----------------
#define AQ_STRIDE 132
#define AV_STRIDE 136
#define AP_STRIDE 68
#define ATTN_U32  (2 * 64 * AQ_STRIDE + 64 * AV_STRIDE + 64 * AP_STRIDE + 2*64 + 2*64 + 3*64)
#define ATTN_SMEM_BYTES (ATTN_U32 * 4)

__global__ __launch_bounds__(256)
void attn_kernel(const float* __restrict__ q, const float* __restrict__ k,
                 const float* __restrict__ v, float* __restrict__ o) {
    extern __shared__ uint32_t smem[];
    uint32_t* Qs = smem;
    uint32_t* Ks = Qs + 64 * AQ_STRIDE;
    uint32_t* Vs = Ks + 64 * AQ_STRIDE;
    uint32_t* Ps = Vs + 64 * AV_STRIDE;
    float* Pmax = (float*)(Ps + 64 * AP_STRIDE);
    float* Psum = Pmax + 128;
    float* Mrow = Psum + 128;
    float* Lrow = Mrow + 64;
    float* Arow = Lrow + 64;

    const int tid  = threadIdx.x;
    const int lane = tid & 31, warp = tid >> 5;
    const int wm = warp & 3, wn = warp >> 2;
    const int g = lane >> 2, t4 = lane & 3;
    const int qt = blockIdx.x, hq = blockIdx.y, b = blockIdx.z;
    const int kvh = hq >> 2;
    const int tok0 = b * SEQ + qt * 64;

    const int r0 = wm * 16 + g, r1 = r0 + 8;

    for (int l = tid; l < 64 * 32; l += 256) {
        int r = l >> 5, d4 = (l & 31) * 4;
        float4 qv = *(const float4*)&q[(size_t)(tok0 + r) * (NH * HD) + hq * HD + d4];
        qv.x *= QK_SCALE; qv.y *= QK_SCALE; qv.z *= QK_SCALE; qv.w *= QK_SCALE;
        *(uint4*)&Qs[r * AQ_STRIDE + d4] = f2tf4(qv);
    }
    if (tid < 64) { Mrow[tid] = -3.0e38f; Lrow[tid] = 0.f; }

    float O[8][4];
#pragma unroll
    for (int nt = 0; nt < 8; nt++)
#pragma unroll
        for (int e = 0; e < 4; e++) O[nt][e] = 0.f;
    __syncthreads();

    for (int kt = 0; kt <= qt; ++kt) {
        for (int l = tid; l < 64 * 32; l += 256) {
            int r = l >> 5, d4 = (l & 31) * 4;
            size_t base = (size_t)(b * SEQ + kt * 64 + r) * (NKV * HD) + kvh * HD + d4;
            *(uint4*)&Ks[r * AQ_STRIDE + d4] = f2tf4(*(const float4*)&k[base]);
            *(uint4*)&Vs[r * AV_STRIDE + d4] = f2tf4(*(const float4*)&v[base]);
        }
        __syncthreads();

        float s[4][4];
#pragma unroll
        for (int nt = 0; nt < 4; nt++)
#pragma unroll
            for (int e = 0; e < 4; e++) s[nt][e] = 0.f;
        {
            const int arow0 = r0 * AQ_STRIDE, arow1 = r1 * AQ_STRIDE;
#pragma unroll
            for (int kb = 0; kb < 128; kb += 8) {
                uint32_t a[4];
                a[0] = Qs[arow0 + kb + t4];
                a[1] = Qs[arow1 + kb + t4];
                a[2] = Qs[arow0 + kb + t4 + 4];
                a[3] = Qs[arow1 + kb + t4 + 4];
#pragma unroll
                for (int nt = 0; nt < 4; nt++) {
                    uint32_t bb[2];
                    int nb = (wn * 32 + nt * 8 + g) * AQ_STRIDE + kb + t4;
                    bb[0] = Ks[nb]; bb[1] = Ks[nb + 4];
                    mma_tf32(s[nt], a, bb);
                }
            }
        }

        if (kt == qt) {
#pragma unroll
            for (int nt = 0; nt < 4; nt++) {
                int c0 = wn * 32 + nt * 8 + 2 * t4;
                if (c0     > r0) s[nt][0] = -1.0e30f;
                if (c0 + 1 > r0) s[nt][1] = -1.0e30f;
                if (c0     > r1) s[nt][2] = -1.0e30f;
                if (c0 + 1 > r1) s[nt][3] = -1.0e30f;
            }
        }

        {
            float mx0 = fmaxf(fmaxf(s[0][0], s[0][1]), fmaxf(s[1][0], s[1][1]));
            mx0 = fmaxf(mx0, fmaxf(fmaxf(s[2][0], s[2][1]), fmaxf(s[3][0], s[3][1])));
            float mx1 = fmaxf(fmaxf(s[0][2], s[0][3]), fmaxf(s[1][2], s[1][3]));
            mx1 = fmaxf(mx1, fmaxf(fmaxf(s[2][2], s[2][3]), fmaxf(s[3][2], s[3][3])));
            mx0 = fmaxf(mx0, __shfl_xor_sync(~0u, mx0, 1));
            mx0 = fmaxf(mx0, __shfl_xor_sync(~0u, mx0, 2));
            mx1 = fmaxf(mx1, __shfl_xor_sync(~0u, mx1, 1));
            mx1 = fmaxf(mx1, __shfl_xor_sync(~0u, mx1, 2));
            if (t4 == 0) { Pmax[wn * 64 + r0] = mx0; Pmax[wn * 64 + r1] = mx1; }
        }
        __syncthreads();

        {
            float mn0 = fmaxf(Mrow[r0], fmaxf(Pmax[r0], Pmax[64 + r0]));
            float mn1 = fmaxf(Mrow[r1], fmaxf(Pmax[r1], Pmax[64 + r1]));
            float sum0 = 0.f, sum1 = 0.f;
#pragma unroll
            for (int nt = 0; nt < 4; nt++) {
                int c = wn * 32 + nt * 8 + 2 * t4;
                float p0 = __expf(s[nt][0] - mn0);
                float p1 = __expf(s[nt][1] - mn0);
                float p2 = __expf(s[nt][2] - mn1);
                float p3 = __expf(s[nt][3] - mn1);
                sum0 += p0 + p1; sum1 += p2 + p3;
                *(uint2*)&Ps[r0 * AP_STRIDE + c] = make_uint2(f2tf(p0), f2tf(p1));
                *(uint2*)&Ps[r1 * AP_STRIDE + c] = make_uint2(f2tf(p2), f2tf(p3));
            }
            sum0 += __shfl_xor_sync(~0u, sum0, 1);
            sum0 += __shfl_xor_sync(~0u, sum0, 2);
            sum1 += __shfl_xor_sync(~0u, sum1, 1);
            sum1 += __shfl_xor_sync(~0u, sum1, 2);
            if (t4 == 0) { Psum[wn * 64 + r0] = sum0; Psum[wn * 64 + r1] = sum1; }
        }
        __syncthreads();

        if (tid < 64) {
            int r = tid;
            float mo = Mrow[r];
            float mn = fmaxf(mo, fmaxf(Pmax[r], Pmax[64 + r]));
            float al = __expf(mo - mn);
            Lrow[r] = Lrow[r] * al + Psum[r] + Psum[64 + r];
            Mrow[r] = mn;
            Arow[r] = al;
        }
        __syncthreads();

        {
            float al0 = Arow[r0], al1 = Arow[r1];
#pragma unroll
            for (int nt = 0; nt < 8; nt++) {
                O[nt][0] *= al0; O[nt][1] *= al0;
                O[nt][2] *= al1; O[nt][3] *= al1;
            }
            const int prow0 = r0 * AP_STRIDE, prow1 = r1 * AP_STRIDE;
#pragma unroll
            for (int kb = 0; kb < 64; kb += 8) {
                uint32_t a[4];
                a[0] = Ps[prow0 + kb + t4];
                a[1] = Ps[prow1 + kb + t4];
                a[2] = Ps[prow0 + kb + t4 + 4];
                a[3] = Ps[prow1 + kb + t4 + 4];
#pragma unroll
                for (int nt = 0; nt < 8; nt++) {
                    uint32_t bb[2];
                    int col = wn * 64 + nt * 8 + g;
                    bb[0] = Vs[(kb + t4) * AV_STRIDE + col];
                    bb[1] = Vs[(kb + t4 + 4) * AV_STRIDE + col];
                    mma_tf32(O[nt], a, bb);
                }
            }
        }
        __syncthreads();
    }

    {
        float inv0 = 1.f / Lrow[r0], inv1 = 1.f / Lrow[r1];
        size_t base0 = (size_t)(tok0 + r0) * (NH * HD) + hq * HD;
        size_t base1 = (size_t)(tok0 + r1) * (NH * HD) + hq * HD;
#pragma unroll
        for (int nt = 0; nt < 8; nt++) {
            int c = wn * 64 + nt * 8 + 2 * t4;
            *(float2*)&o[base0 + c] = make_float2(O[nt][0] * inv0, O[nt][1] * inv0);
            *(float2*)&o[base1 + c] = make_float2(O[nt][2] * inv1, O[nt][3] * inv1);
        }
    }
}

// ---------------- host orchestration ----------------
extern "C" void kernel_launch(void* const* d_in, const int* in_sizes, int n_in,
                              void* d_out, int out_size) {
    const float* x    = (const float*)d_in[0];
    const float* cosb = (const float*)d_in[2];
    const float* sinb = (const float*)d_in[3];
    const float* wq   = (const float*)d_in[4];
    const float* bq   = (const float*)d_in[5];
    const float* wk   = (const float*)d_in[6];
    const float* bk   = (const float*)d_in[7];
    const float* wv   = (const float*)d_in[8];
    const float* bv   = (const float*)d_in[9];
    const float* wo   = (const float*)d_in[10];
    const float* qnw  = (const float*)d_in[11];
    const float* knw  = (const float*)d_in[12];
    const float* ln1  = (const float*)d_in[13];
    const float* ln2  = (const float*)d_in[14];
    const float* wg   = (const float*)d_in[15];
    const float* wu   = (const float*)d_in[16];
    const float* wd   = (const float*)d_in[17];
    float* out = (float*)d_out;

    float *h_, *q_, *k_, *v_, *attn_, *x1_, *gate_;
    cudaGetSymbolAddress((void**)&h_,    g_h);
    cudaGetSymbolAddress((void**)&q_,    g_q);
    cudaGetSymbolAddress((void**)&k_,    g_k);
    cudaGetSymbolAddress((void**)&v_,    g_v);
    cudaGetSymbolAddress((void**)&attn_, g_attn);
    cudaGetSymbolAddress((void**)&x1_,   g_x1);
    cudaGetSymbolAddress((void**)&gate_, g_gate);

    cudaFuncSetAttribute(attn_kernel, cudaFuncAttributeMaxDynamicSharedMemorySize, ATTN_SMEM_BYTES);
    cudaFuncSetAttribute(gemm_std,  cudaFuncAttributeMaxDynamicSharedMemorySize, GEMM_SMEM_BYTES);
    cudaFuncSetAttribute(gemm_silu, cudaFuncAttributeMaxDynamicSharedMemorySize, GEMM_SMEM_BYTES);

    // 1. h = RMSNorm(x, ln1)
    rmsnorm_kernel<<<TTOK, 256>>>(x, ln1, h_);
    // 2-4. q/k/v projections
    gemm_std<<<dim3(HIDN / 128, TTOK / 128), 256, GEMM_SMEM_BYTES>>>(h_, wq, bq, nullptr, q_, NH * HD, HIDN);
    gemm_std<<<dim3((NKV * HD) / 128, TTOK / 128), 256, GEMM_SMEM_BYTES>>>(h_, wk, bk, nullptr, k_, NKV * HD, HIDN);
    gemm_std<<<dim3((NKV * HD) / 128, TTOK / 128), 256, GEMM_SMEM_BYTES>>>(h_, wv, bv, nullptr, v_, NKV * HD, HIDN);
    // 5. per-head RMSNorm + RoPE
    qknorm_rope_kernel<<<dim3(TTOK, NH + NKV), 128>>>(q_, k_, qnw, knw, cosb, sinb);
    // 6. causal flash attention (tf32 MMA)
    attn_kernel<<<dim3(SEQ / 64, NH, BATCH), 256, ATTN_SMEM_BYTES>>>(q_, k_, v_, attn_);
    // 7. x1 = x + attn @ wo^T
    gemm_std<<<dim3(HIDN / 128, TTOK / 128), 256, GEMM_SMEM_BYTES>>>(attn_, wo, nullptr, x, x1_, HIDN, HIDN);
    // 8. h2 = RMSNorm(x1, ln2)
    rmsnorm_kernel<<<TTOK, 256>>>(x1_, ln2, h_);
    // 9. gate projection
    gemm_std<<<dim3(INTERN / 128, TTOK / 128), 256, GEMM_SMEM_BYTES>>>(h_, wg, nullptr, nullptr, gate_, INTERN, HIDN);
    // 10. up projection, fused: gate <- silu(gate) * up
    gemm_silu<<<dim3(INTERN / 128, TTOK / 128), 256, GEMM_SMEM_BYTES>>>(h_, wu, gate_, gate_, INTERN, HIDN);
    // 11. out = x1 + gate @ wd^T
    gemm_std<<<dim3(HIDN / 128, TTOK / 128), 256, GEMM_SMEM_BYTES>>>(gate_, wd, nullptr, x1_, out, HIDN, INTERN);
}

// round 8
// speedup vs baseline: 1.8665x; 1.3332x over previous
#include <cuda_runtime.h>
#include <cuda_fp16.h>
#include <cstdint>

#define HIDN   2048
#define NH     16
#define NKV    4
#define HD     128
#define INTERN 8192
#define BATCH  4
#define SEQ    1024
#define TTOK   (BATCH*SEQ)   /* 4096 */
#define EPSV   1e-6f
#define QK_SCALE 0.08838834764831845f  /* 1/sqrt(128) */
#define QKV_LD (NH*HD + 2*NKV*HD)      /* 3072 */

// ---------------- scratch ----------------
__device__ __half g_h16   [TTOK * HIDN];
__device__ float  g_qkv   [TTOK * QKV_LD];
__device__ __half g_attn16[TTOK * HIDN];
__device__ float  g_x1    [TTOK * HIDN];
__device__ float  g_gu    [TTOK * 2 * INTERN];
__device__ __half g_act16 [TTOK * INTERN];
// fp16 weights
__device__ __half g_wqkv16[QKV_LD * HIDN];
__device__ __half g_wo16  [HIDN * HIDN];
__device__ __half g_wgu16 [2 * INTERN * HIDN];
__device__ __half g_wd16  [HIDN * INTERN];
__device__ float  g_bqkv  [QKV_LD];

// ---------------- helpers ----------------
__device__ __forceinline__ uint32_t f2tf(float f) {
    uint32_t u; asm("cvt.rna.tf32.f32 %0, %1;" : "=r"(u) : "f"(f)); return u;
}
__device__ __forceinline__ uint4 f2tf4(float4 v) {
    uint4 u; u.x = f2tf(v.x); u.y = f2tf(v.y); u.z = f2tf(v.z); u.w = f2tf(v.w); return u;
}
__device__ __forceinline__ void mma_tf32(float c[4], const uint32_t a[4], const uint32_t b[2]) {
    asm volatile("mma.sync.aligned.m16n8k8.row.col.f32.tf32.tf32.f32 "
        "{%0,%1,%2,%3}, {%4,%5,%6,%7}, {%8,%9}, {%0,%1,%2,%3};\n"
        : "+f"(c[0]), "+f"(c[1]), "+f"(c[2]), "+f"(c[3])
        : "r"(a[0]), "r"(a[1]), "r"(a[2]), "r"(a[3]), "r"(b[0]), "r"(b[1]));
}
__device__ __forceinline__ void mma_f16(float c[4], const uint32_t a[4], const uint32_t b[2]) {
    asm volatile("mma.sync.aligned.m16n8k16.row.col.f32.f16.f16.f32 "
        "{%0,%1,%2,%3}, {%4,%5,%6,%7}, {%8,%9}, {%0,%1,%2,%3};\n"
        : "+f"(c[0]), "+f"(c[1]), "+f"(c[2]), "+f"(c[3])
        : "r"(a[0]), "r"(a[1]), "r"(a[2]), "r"(a[3]), "r"(b[0]), "r"(b[1]));
}
__device__ __forceinline__ uint32_t pack_h2(float lo, float hi) {
    __half2 h = __floats2half2_rn(lo, hi);
    return *(uint32_t*)&h;
}

#define CP16(dst, src) \
    asm volatile("cp.async.cg.shared.global [%0], [%1], 16;" :: "r"(dst), "l"(src))
#define CP_COMMIT() asm volatile("cp.async.commit_group;")
#define CP_WAIT(n)  asm volatile("cp.async.wait_group %0;" :: "n"(n))

// ---------------- fp16 GEMM with cp.async 4-stage pipeline ----------------
// C[M,ldc] = A[M,K](fp16) @ B[N,K]^T(fp16) (+bias)(+res), fp32 out.
// BM=BN=128, BK=32. 256 thr, 8 warps (2M x 4N), warp tile 64x32.
// smem per stage: A 128 rows x 20 u32 (16 data + 4 pad) = 10240 B, B same.
#define STAGES 4
#define STAGE_BYTES 20480
#define GEMM_SMEM_BYTES (STAGES * STAGE_BYTES)   /* 81920 */

__global__ __launch_bounds__(256, 2)
void gemm_f16(const __half* __restrict__ A, const __half* __restrict__ B,
              const float* __restrict__ bias, const float* __restrict__ res,
              float* __restrict__ C, int ldc, int K) {
    extern __shared__ uint8_t smem_raw[];
    const int tid  = threadIdx.x;
    const int lane = tid & 31, warp = tid >> 5;
    const int wm = warp & 1, wn = warp >> 1;
    const int g  = lane >> 2, t4 = lane & 3;
    const int brow = blockIdx.y << 7, bcol = blockIdx.x << 7;

    // loader: rows (ar, ar+64), chunk achk (16 B = 8 halves); 4 cp.async / thread / tile
    const int ar = tid >> 2, achk = tid & 3;
    const __half* ag0 = A + (size_t)(brow + ar) * K + achk * 8;
    const __half* ag1 = ag0 + (size_t)64 * K;
    const __half* bg0 = B + (size_t)(bcol + ar) * K + achk * 8;
    const __half* bg1 = bg0 + (size_t)64 * K;

    const uint32_t sbase = (uint32_t)__cvta_generic_to_shared(smem_raw);
    const uint32_t sA0 = ar * 80 + achk * 16;
    const uint32_t sA1 = sA0 + 64 * 80;
    const uint32_t sB0 = 10240 + sA0;
    const uint32_t sB1 = 10240 + sA1;

    float acc[4][4][4];
#pragma unroll
    for (int i = 0; i < 4; i++)
#pragma unroll
        for (int j = 0; j < 4; j++)
#pragma unroll
            for (int e = 0; e < 4; e++) acc[i][j][e] = 0.f;

    const int nk = K >> 5;   // nk >= 64 for all our shapes

    // preload stages 0..2
#pragma unroll
    for (int s = 0; s < STAGES - 1; ++s) {
        uint32_t st = sbase + s * STAGE_BYTES;
        CP16(st + sA0, ag0 + s * 32);
        CP16(st + sA1, ag1 + s * 32);
        CP16(st + sB0, bg0 + s * 32);
        CP16(st + sB1, bg1 + s * 32);
        CP_COMMIT();
    }

    for (int t = 0; t < nk; ++t) {
        CP_WAIT(STAGES - 2);
        __syncthreads();
        const int tn = t + STAGES - 1;
        if (tn < nk) {
            uint32_t st = sbase + (tn & (STAGES - 1)) * STAGE_BYTES;
            CP16(st + sA0, ag0 + tn * 32);
            CP16(st + sA1, ag1 + tn * 32);
            CP16(st + sB0, bg0 + tn * 32);
            CP16(st + sB1, bg1 + tn * 32);
            CP_COMMIT();
        }
        const uint32_t* As_ = (const uint32_t*)(smem_raw + (t & (STAGES - 1)) * STAGE_BYTES);
        const uint32_t* Bs_ = As_ + 2560;
#pragma unroll
        for (int kb = 0; kb < 16; kb += 8) {
            uint32_t af[4][4], bf[4][2];
#pragma unroll
            for (int mt = 0; mt < 4; ++mt) {
                int base = (wm * 64 + mt * 16 + g) * 20 + kb + t4;
                af[mt][0] = As_[base];
                af[mt][1] = As_[base + 8 * 20];
                af[mt][2] = As_[base + 4];
                af[mt][3] = As_[base + 8 * 20 + 4];
            }
#pragma unroll
            for (int nt = 0; nt < 4; ++nt) {
                int nbase = (wn * 32 + nt * 8 + g) * 20 + kb + t4;
                bf[nt][0] = Bs_[nbase];
                bf[nt][1] = Bs_[nbase + 4];
            }
#pragma unroll
            for (int mt = 0; mt < 4; ++mt)
#pragma unroll
                for (int nt = 0; nt < 4; ++nt)
                    mma_f16(acc[mt][nt], af[mt], bf[nt]);
        }
    }

    // epilogue
#pragma unroll
    for (int mt = 0; mt < 4; ++mt) {
        int r0 = brow + wm * 64 + mt * 16 + g;
#pragma unroll
        for (int nt = 0; nt < 4; ++nt) {
            int c0 = bcol + wn * 32 + nt * 8 + t4 * 2;
            float2 v0 = make_float2(acc[mt][nt][0], acc[mt][nt][1]);
            float2 v1 = make_float2(acc[mt][nt][2], acc[mt][nt][3]);
            if (bias) {
                float2 bv = *(const float2*)&bias[c0];
                v0.x += bv.x; v0.y += bv.y; v1.x += bv.x; v1.y += bv.y;
            }
            if (res) {
                float2 ra = *(const float2*)&res[(size_t)r0 * ldc + c0];
                float2 rb = *(const float2*)&res[(size_t)(r0 + 8) * ldc + c0];
                v0.x += ra.x; v0.y += ra.y; v1.x += rb.x; v1.y += rb.y;
            }
            *(float2*)&C[(size_t)r0 * ldc + c0]       = v0;
            *(float2*)&C[(size_t)(r0 + 8) * ldc + c0] = v1;
        }
    }
}

// ---------------- fp32 -> fp16 convert (8 elems / thread) ----------------
__global__ void cvt16_kernel(const float* __restrict__ src, __half* __restrict__ dst, int n8) {
    int i = blockIdx.x * blockDim.x + threadIdx.x;
    if (i < n8) {
        float4 a = ((const float4*)src)[2 * i];
        float4 b = ((const float4*)src)[2 * i + 1];
        uint4 o;
        o.x = pack_h2(a.x, a.y); o.y = pack_h2(a.z, a.w);
        o.z = pack_h2(b.x, b.y); o.w = pack_h2(b.z, b.w);
        ((uint4*)dst)[i] = o;
    }
}

__global__ void pack_bias_kernel(const float* __restrict__ bq, const float* __restrict__ bk,
                                 const float* __restrict__ bv, float* __restrict__ dst) {
    int i = blockIdx.x * blockDim.x + threadIdx.x;
    if (i < QKV_LD)
        dst[i] = (i < 2048) ? bq[i] : ((i < 2560) ? bk[i - 2048] : bv[i - 2560]);
}

// ---------------- RMSNorm -> fp16 ----------------
__global__ void rmsnorm16_kernel(const float* __restrict__ x, const float* __restrict__ w,
                                 __half* __restrict__ out) {
    int row = blockIdx.x;
    const float* xr = x + (size_t)row * HIDN;
    float4 v[2];
    float ss = 0.f;
#pragma unroll
    for (int i = 0; i < 2; i++) {
        v[i] = *(const float4*)&xr[(threadIdx.x + i * 256) * 4];
        ss += v[i].x * v[i].x + v[i].y * v[i].y + v[i].z * v[i].z + v[i].w * v[i].w;
    }
#pragma unroll
    for (int o = 16; o; o >>= 1) ss += __shfl_xor_sync(~0u, ss, o);
    __shared__ float red[8];
    if ((threadIdx.x & 31) == 0) red[threadIdx.x >> 5] = ss;
    __syncthreads();
    if (threadIdx.x == 0) {
        float t = 0.f;
#pragma unroll
        for (int i = 0; i < 8; i++) t += red[i];
        red[0] = rsqrtf(t / (float)HIDN + EPSV);
    }
    __syncthreads();
    float r = red[0];
#pragma unroll
    for (int i = 0; i < 2; i++) {
        int c = (threadIdx.x + i * 256) * 4;
        float4 wv = *(const float4*)&w[c];
        uint2 o2;
        o2.x = pack_h2(v[i].x * r * wv.x, v[i].y * r * wv.y);
        o2.y = pack_h2(v[i].z * r * wv.z, v[i].w * r * wv.w);
        *(uint2*)&out[(size_t)row * HIDN + c] = o2;
    }
}

// ---------------- per-head RMSNorm + RoPE on packed qkv (fp32, in place) ----------------
__global__ void qknorm_rope_kernel(float* __restrict__ qkv,
                                   const float* __restrict__ qw, const float* __restrict__ kw,
                                   const float* __restrict__ cs, const float* __restrict__ sn) {
    int token = blockIdx.x, h = blockIdx.y;   // h: 0..15 q heads, 16..19 k heads
    float* p; const float* w;
    if (h < NH) { p = qkv + (size_t)token * QKV_LD + h * HD;              w = qw; }
    else        { p = qkv + (size_t)token * QKV_LD + 2048 + (h - NH) * HD; w = kw; }
    int d = threadIdx.x;
    float v = p[d];
    float ss = v * v;
#pragma unroll
    for (int o = 16; o; o >>= 1) ss += __shfl_xor_sync(~0u, ss, o);
    __shared__ float red[4];
    __shared__ float sh[128];
    if ((d & 31) == 0) red[d >> 5] = ss;
    __syncthreads();
    float tot = red[0] + red[1] + red[2] + red[3];
    float r = rsqrtf(tot / 128.f + EPSV);
    float xn = v * r * w[d];
    sh[d] = xn;
    __syncthreads();
    float rot = (d < 64) ? -sh[d + 64] : sh[d - 64];
    float c = cs[(size_t)token * 128 + d], s = sn[(size_t)token * 128 + d];
    p[d] = xn * c + rot * s;
}

// ---------------- flash attention (tf32 MMA, causal, GQA) ----------------
// reads packed qkv (fp32, ld=3072), writes fp16 output.
#define AQ_STRIDE 132
#define AV_STRIDE 136
#define AP_STRIDE 68
#define ATTN_U32  (2 * 64 * AQ_STRIDE + 64 * AV_STRIDE + 64 * AP_STRIDE + 2*64 + 2*64 + 3*64)
#define ATTN_SMEM_BYTES (ATTN_U32 * 4)

__global__ __launch_bounds__(256)
void attn_kernel(const float* __restrict__ qkv, __half* __restrict__ o16) {
    extern __shared__ uint32_t smem[];
    uint32_t* Qs = smem;
    uint32_t* Ks = Qs + 64 * AQ_STRIDE;
    uint32_t* Vs = Ks + 64 * AQ_STRIDE;
    uint32_t* Ps = Vs + 64 * AV_STRIDE;
    float* Pmax = (float*)(Ps + 64 * AP_STRIDE);
    float* Psum = Pmax + 128;
    float* Mrow = Psum + 128;
    float* Lrow = Mrow + 64;
    float* Arow = Lrow + 64;

    const int tid  = threadIdx.x;
    const int lane = tid & 31, warp = tid >> 5;
    const int wm = warp & 3, wn = warp >> 2;
    const int g = lane >> 2, t4 = lane & 3;
    const int qt = blockIdx.x, hq = blockIdx.y, b = blockIdx.z;
    const int kvh = hq >> 2;
    const int tok0 = b * SEQ + qt * 64;

    const int r0 = wm * 16 + g, r1 = r0 + 8;

    for (int l = tid; l < 64 * 32; l += 256) {
        int r = l >> 5, d4 = (l & 31) * 4;
        float4 qv = *(const float4*)&qkv[(size_t)(tok0 + r) * QKV_LD + hq * HD + d4];
        qv.x *= QK_SCALE; qv.y *= QK_SCALE; qv.z *= QK_SCALE; qv.w *= QK_SCALE;
        *(uint4*)&Qs[r * AQ_STRIDE + d4] = f2tf4(qv);
    }
    if (tid < 64) { Mrow[tid] = -3.0e38f; Lrow[tid] = 0.f; }

    float O[8][4];
#pragma unroll
    for (int nt = 0; nt < 8; nt++)
#pragma unroll
        for (int e = 0; e < 4; e++) O[nt][e] = 0.f;
    __syncthreads();

    for (int kt = 0; kt <= qt; ++kt) {
        for (int l = tid; l < 64 * 32; l += 256) {
            int r = l >> 5, d4 = (l & 31) * 4;
            size_t base = (size_t)(b * SEQ + kt * 64 + r) * QKV_LD + d4;
            *(uint4*)&Ks[r * AQ_STRIDE + d4] = f2tf4(*(const float4*)&qkv[base + 2048 + kvh * HD]);
            *(uint4*)&Vs[r * AV_STRIDE + d4] = f2tf4(*(const float4*)&qkv[base + 2560 + kvh * HD]);
        }
        __syncthreads();

        float s[4][4];
#pragma unroll
        for (int nt = 0; nt < 4; nt++)
#pragma unroll
            for (int e = 0; e < 4; e++) s[nt][e] = 0.f;
        {
            const int arow0 = r0 * AQ_STRIDE, arow1 = r1 * AQ_STRIDE;
#pragma unroll
            for (int kb = 0; kb < 128; kb += 8) {
                uint32_t a[4];
                a[0] = Qs[arow0 + kb + t4];
                a[1] = Qs[arow1 + kb + t4];
                a[2] = Qs[arow0 + kb + t4 + 4];
                a[3] = Qs[arow1 + kb + t4 + 4];
#pragma unroll
                for (int nt = 0; nt < 4; nt++) {
                    uint32_t bb[2];
                    int nb = (wn * 32 + nt * 8 + g) * AQ_STRIDE + kb + t4;
                    bb[0] = Ks[nb]; bb[1] = Ks[nb + 4];
                    mma_tf32(s[nt], a, bb);
                }
            }
        }

        if (kt == qt) {
#pragma unroll
            for (int nt = 0; nt < 4; nt++) {
                int c0 = wn * 32 + nt * 8 + 2 * t4;
                if (c0     > r0) s[nt][0] = -1.0e30f;
                if (c0 + 1 > r0) s[nt][1] = -1.0e30f;
                if (c0     > r1) s[nt][2] = -1.0e30f;
                if (c0 + 1 > r1) s[nt][3] = -1.0e30f;
            }
        }

        {
            float mx0 = fmaxf(fmaxf(s[0][0], s[0][1]), fmaxf(s[1][0], s[1][1]));
            mx0 = fmaxf(mx0, fmaxf(fmaxf(s[2][0], s[2][1]), fmaxf(s[3][0], s[3][1])));
            float mx1 = fmaxf(fmaxf(s[0][2], s[0][3]), fmaxf(s[1][2], s[1][3]));
            mx1 = fmaxf(mx1, fmaxf(fmaxf(s[2][2], s[2][3]), fmaxf(s[3][2], s[3][3])));
            mx0 = fmaxf(mx0, __shfl_xor_sync(~0u, mx0, 1));
            mx0 = fmaxf(mx0, __shfl_xor_sync(~0u, mx0, 2));
            mx1 = fmaxf(mx1, __shfl_xor_sync(~0u, mx1, 1));
            mx1 = fmaxf(mx1, __shfl_xor_sync(~0u, mx1, 2));
            if (t4 == 0) { Pmax[wn * 64 + r0] = mx0; Pmax[wn * 64 + r1] = mx1; }
        }
        __syncthreads();

        {
            float mn0 = fmaxf(Mrow[r0], fmaxf(Pmax[r0], Pmax[64 + r0]));
            float mn1 = fmaxf(Mrow[r1], fmaxf(Pmax[r1], Pmax[64 + r1]));
            float sum0 = 0.f, sum1 = 0.f;
#pragma unroll
            for (int nt = 0; nt < 4; nt++) {
                int c = wn * 32 + nt * 8 + 2 * t4;
                float p0 = __expf(s[nt][0] - mn0);
                float p1 = __expf(s[nt][1] - mn0);
                float p2 = __expf(s[nt][2] - mn1);
                float p3 = __expf(s[nt][3] - mn1);
                sum0 += p0 + p1; sum1 += p2 + p3;
                *(uint2*)&Ps[r0 * AP_STRIDE + c] = make_uint2(f2tf(p0), f2tf(p1));
                *(uint2*)&Ps[r1 * AP_STRIDE + c] = make_uint2(f2tf(p2), f2tf(p3));
            }
            sum0 += __shfl_xor_sync(~0u, sum0, 1);
            sum0 += __shfl_xor_sync(~0u, sum0, 2);
            sum1 += __shfl_xor_sync(~0u, sum1, 1);
            sum1 += __shfl_xor_sync(~0u, sum1, 2);
            if (t4 == 0) { Psum[wn * 64 + r0] = sum0; Psum[wn * 64 + r1] = sum1; }
        }
        __syncthreads();

        if (tid < 64) {
            int r = tid;
            float mo = Mrow[r];
            float mn = fmaxf(mo, fmaxf(Pmax[r], Pmax[64 + r]));
            float al = __expf(mo - mn);
            Lrow[r] = Lrow[r] * al + Psum[r] + Psum[64 + r];
            Mrow[r] = mn;
            Arow[r] = al;
        }
        __syncthreads();

        {
            float al0 = Arow[r0], al1 = Arow[r1];
#pragma unroll
            for (int nt = 0; nt < 8; nt++) {
                O[nt][0] *= al0; O[nt][1] *= al0;
                O[nt][2] *= al1; O[nt][3] *= al1;
            }
            const int prow0 = r0 * AP_STRIDE, prow1 = r1 * AP_STRIDE;
#pragma unroll
            for (int kb = 0; kb < 64; kb += 8) {
                uint32_t a[4];
                a[0] = Ps[prow0 + kb + t4];
                a[1] = Ps[prow1 + kb + t4];
                a[2] = Ps[prow0 + kb + t4 + 4];
                a[3] = Ps[prow1 + kb + t4 + 4];
#pragma unroll
                for (int nt = 0; nt < 8; nt++) {
                    uint32_t bb[2];
                    int col = wn * 64 + nt * 8 + g;
                    bb[0] = Vs[(kb + t4) * AV_STRIDE + col];
                    bb[1] = Vs[(kb + t4 + 4) * AV_STRIDE + col];
                    mma_tf32(O[nt], a, bb);
                }
            }
        }
        __syncthreads();
    }

    {
        float inv0 = 1.f / Lrow[r0], inv1 = 1.f / Lrow[r1];
        size_t base0 = (size_t)(tok0 + r0) * (NH * HD) + hq * HD;
        size_t base1 = (size_t)(tok0 + r1) * (NH * HD) + hq * HD;
#pragma unroll
        for (int nt = 0; nt < 8; nt++) {
            int c = wn * 64 + nt * 8 + 2 * t4;
            *(uint32_t*)&o16[base0 + c] = pack_h2(O[nt][0] * inv0, O[nt][1] * inv0);
            *(uint32_t*)&o16[base1 + c] = pack_h2(O[nt][2] * inv1, O[nt][3] * inv1);
        }
    }
}

// ---------------- silu(gate)*up -> fp16 ----------------
__global__ void silu16_kernel(const float* __restrict__ gu, __half* __restrict__ act, int n8) {
    int i = blockIdx.x * blockDim.x + threadIdx.x;
    if (i >= n8) return;
    int r = i >> 10;                 // INTER/8 = 1024 chunks per row
    int c8 = (i & 1023) * 8;
    const float* gp = gu + (size_t)r * (2 * INTERN) + c8;
    const float* up = gp + INTERN;
    float4 g0 = *(const float4*)gp,       g1 = *(const float4*)(gp + 4);
    float4 u0 = *(const float4*)up,       u1 = *(const float4*)(up + 4);
    g0.x = g0.x / (1.f + __expf(-g0.x)) * u0.x;
    g0.y = g0.y / (1.f + __expf(-g0.y)) * u0.y;
    g0.z = g0.z / (1.f + __expf(-g0.z)) * u0.z;
    g0.w = g0.w / (1.f + __expf(-g0.w)) * u0.w;
    g1.x = g1.x / (1.f + __expf(-g1.x)) * u1.x;
    g1.y = g1.y / (1.f + __expf(-g1.y)) * u1.y;
    g1.z = g1.z / (1.f + __expf(-g1.z)) * u1.z;
    g1.w = g1.w / (1.f + __expf(-g1.w)) * u1.w;
    uint4 o;
    o.x = pack_h2(g0.x, g0.y); o.y = pack_h2(g0.z, g0.w);
    o.z = pack_h2(g1.x, g1.y); o.w = pack_h2(g1.z, g1.w);
    ((uint4*)act)[i] = o;
}

// ---------------- host orchestration ----------------
extern "C" void kernel_launch(void* const* d_in, const int* in_sizes, int n_in,
                              void* d_out, int out_size) {
    const float* x    = (const float*)d_in[0];
    const float* cosb = (const float*)d_in[2];
    const float* sinb = (const float*)d_in[3];
    const float* wq   = (const float*)d_in[4];
    const float* bq   = (const float*)d_in[5];
    const float* wk   = (const float*)d_in[6];
    const float* bk   = (const float*)d_in[7];
    const float* wv   = (const float*)d_in[8];
    const float* bv   = (const float*)d_in[9];
    const float* wo   = (const float*)d_in[10];
    const float* qnw  = (const float*)d_in[11];
    const float* knw  = (const float*)d_in[12];
    const float* ln1  = (const float*)d_in[13];
    const float* ln2  = (const float*)d_in[14];
    const float* wg   = (const float*)d_in[15];
    const float* wu   = (const float*)d_in[16];
    const float* wd   = (const float*)d_in[17];
    float* out = (float*)d_out;

    __half *h16, *attn16, *act16, *wqkv16, *wo16, *wgu16, *wd16;
    float *qkv_, *x1_, *gu_, *bqkv;
    cudaGetSymbolAddress((void**)&h16,    g_h16);
    cudaGetSymbolAddress((void**)&attn16, g_attn16);
    cudaGetSymbolAddress((void**)&act16,  g_act16);
    cudaGetSymbolAddress((void**)&wqkv16, g_wqkv16);
    cudaGetSymbolAddress((void**)&wo16,   g_wo16);
    cudaGetSymbolAddress((void**)&wgu16,  g_wgu16);
    cudaGetSymbolAddress((void**)&wd16,   g_wd16);
    cudaGetSymbolAddress((void**)&qkv_,   g_qkv);
    cudaGetSymbolAddress((void**)&x1_,    g_x1);
    cudaGetSymbolAddress((void**)&gu_,    g_gu);
    cudaGetSymbolAddress((void**)&bqkv,   g_bqkv);

    cudaFuncSetAttribute(attn_kernel, cudaFuncAttributeMaxDynamicSharedMemorySize, ATTN_SMEM_BYTES);
    cudaFuncSetAttribute(gemm_f16,    cudaFuncAttributeMaxDynamicSharedMemorySize, GEMM_SMEM_BYTES);

    // 0. weight conversion / packing (fp32 -> fp16)
    {
        const int T = 256;
        cvt16_kernel<<<(2048*2048/8 + T-1)/T, T>>>(wq, wqkv16,                 2048*2048/8);
        cvt16_kernel<<<( 512*2048/8 + T-1)/T, T>>>(wk, wqkv16 + 2048*2048,      512*2048/8);
        cvt16_kernel<<<( 512*2048/8 + T-1)/T, T>>>(wv, wqkv16 + 2560*2048,      512*2048/8);
        cvt16_kernel<<<(2048*2048/8 + T-1)/T, T>>>(wo, wo16,                   2048*2048/8);
        cvt16_kernel<<<(8192*2048/8 + T-1)/T, T>>>(wg, wgu16,                  8192*2048/8);
        cvt16_kernel<<<(8192*2048/8 + T-1)/T, T>>>(wu, wgu16 + 8192*2048,      8192*2048/8);
        cvt16_kernel<<<(2048*8192/8 + T-1)/T, T>>>(wd, wd16,                   2048*8192/8);
        pack_bias_kernel<<<(QKV_LD + T-1)/T, T>>>(bq, bk, bv, bqkv);
    }

    // 1. h16 = (half) RMSNorm(x, ln1)
    rmsnorm16_kernel<<<TTOK, 256>>>(x, ln1, h16);
    // 2. packed QKV projection: qkv = h16 @ wqkv^T + bqkv   (single 768-CTA GEMM)
    gemm_f16<<<dim3(QKV_LD/128, TTOK/128), 256, GEMM_SMEM_BYTES>>>(h16, wqkv16, bqkv, nullptr, qkv_, QKV_LD, HIDN);
    // 3. per-head RMSNorm + RoPE (in place, packed)
    qknorm_rope_kernel<<<dim3(TTOK, NH + NKV), 128>>>(qkv_, qnw, knw, cosb, sinb);
    // 4. causal flash attention -> fp16
    attn_kernel<<<dim3(SEQ/64, NH, BATCH), 256, ATTN_SMEM_BYTES>>>(qkv_, attn16);
    // 5. x1 = x + attn @ wo^T
    gemm_f16<<<dim3(HIDN/128, TTOK/128), 256, GEMM_SMEM_BYTES>>>(attn16, wo16, nullptr, x, x1_, HIDN, HIDN);
    // 6. h16 = (half) RMSNorm(x1, ln2)
    rmsnorm16_kernel<<<TTOK, 256>>>(x1_, ln2, h16);
    // 7. gate|up projection (single 4096-CTA GEMM)
    gemm_f16<<<dim3(2*INTERN/128, TTOK/128), 256, GEMM_SMEM_BYTES>>>(h16, wgu16, nullptr, nullptr, gu_, 2*INTERN, HIDN);
    // 8. act16 = (half)(silu(gate) * up)
    silu16_kernel<<<TTOK*INTERN/8/256, 256>>>(gu_, act16, TTOK*INTERN/8);
    // 9. out = x1 + act @ wd^T
    gemm_f16<<<dim3(HIDN/128, TTOK/128), 256, GEMM_SMEM_BYTES>>>(act16, wd16, nullptr, x1_, out, HIDN, INTERN);
}

// round 9
// speedup vs baseline: 1.9999x; 1.0715x over previous
#include <cuda_runtime.h>
#include <cuda_fp16.h>
#include <cstdint>

#define HIDN   2048
#define NH     16
#define NKV    4
#define HD     128
#define INTERN 8192
#define BATCH  4
#define SEQ    1024
#define TTOK   (BATCH*SEQ)   /* 4096 */
#define EPSV   1e-6f
#define QK_SCALE 0.08838834764831845f  /* 1/sqrt(128) */
#define QKV_LD (NH*HD + 2*NKV*HD)      /* 3072 */

// ---------------- scratch ----------------
__device__ __half g_h16   [TTOK * HIDN];
__device__ float  g_qkv   [TTOK * QKV_LD];
__device__ __half g_attn16[TTOK * HIDN];
__device__ float  g_x1    [TTOK * HIDN];
__device__ __half g_gu16  [TTOK * 2 * INTERN];
__device__ __half g_act16 [TTOK * INTERN];
// fp16 weights
__device__ __half g_wqkv16[QKV_LD * HIDN];
__device__ __half g_wo16  [HIDN * HIDN];
__device__ __half g_wgu16 [2 * INTERN * HIDN];
__device__ __half g_wd16  [HIDN * INTERN];
__device__ float  g_bqkv  [QKV_LD];

// ---------------- helpers ----------------
__device__ __forceinline__ void mma_f16(float c[4], const uint32_t a[4], const uint32_t b[2]) {
    asm volatile("mma.sync.aligned.m16n8k16.row.col.f32.f16.f16.f32 "
        "{%0,%1,%2,%3}, {%4,%5,%6,%7}, {%8,%9}, {%0,%1,%2,%3};\n"
        : "+f"(c[0]), "+f"(c[1]), "+f"(c[2]), "+f"(c[3])
        : "r"(a[0]), "r"(a[1]), "r"(a[2]), "r"(a[3]), "r"(b[0]), "r"(b[1]));
}
__device__ __forceinline__ uint32_t pack_h2(float lo, float hi) {
    __half2 h = __floats2half2_rn(lo, hi);
    return *(uint32_t*)&h;
}
__device__ __forceinline__ float2 unpack_h2(uint32_t u) {
    return __half22float2(*(__half2*)&u);
}

#define CP16(dst, src) \
    asm volatile("cp.async.cg.shared.global [%0], [%1], 16;" :: "r"(dst), "l"(src))
#define CP_COMMIT() asm volatile("cp.async.commit_group;")
#define CP_WAIT(n)  asm volatile("cp.async.wait_group %0;" :: "n"(n))

// ---------------- fp16 GEMM with cp.async 4-stage pipeline ----------------
// C[M,ldc] = A[M,K](fp16) @ B[N,K]^T(fp16) (+bias)(+res).
// BM=BN=128, BK=32. 256 thr, 8 warps (2M x 4N), warp tile 64x32.
#define STAGES 4
#define STAGE_BYTES 20480
#define GEMM_SMEM_BYTES (STAGES * STAGE_BYTES)   /* 81920 */

// OUT16=0: float C; OUT16=1: half C (no bias/res)
template<int OUT16>
__device__ __forceinline__ void gemm_core(
    const __half* __restrict__ A, const __half* __restrict__ B,
    const float* __restrict__ bias, const float* __restrict__ res,
    void* __restrict__ Cv, int ldc, int K)
{
    extern __shared__ uint8_t smem_raw[];
    const int tid  = threadIdx.x;
    const int lane = tid & 31, warp = tid >> 5;
    const int wm = warp & 1, wn = warp >> 1;
    const int g  = lane >> 2, t4 = lane & 3;
    const int brow = blockIdx.y << 7, bcol = blockIdx.x << 7;

    const int ar = tid >> 2, achk = tid & 3;
    const __half* ag0 = A + (size_t)(brow + ar) * K + achk * 8;
    const __half* ag1 = ag0 + (size_t)64 * K;
    const __half* bg0 = B + (size_t)(bcol + ar) * K + achk * 8;
    const __half* bg1 = bg0 + (size_t)64 * K;

    const uint32_t sbase = (uint32_t)__cvta_generic_to_shared(smem_raw);
    const uint32_t sA0 = ar * 80 + achk * 16;
    const uint32_t sA1 = sA0 + 64 * 80;
    const uint32_t sB0 = 10240 + sA0;
    const uint32_t sB1 = 10240 + sA1;

    float acc[4][4][4];
#pragma unroll
    for (int i = 0; i < 4; i++)
#pragma unroll
        for (int j = 0; j < 4; j++)
#pragma unroll
            for (int e = 0; e < 4; e++) acc[i][j][e] = 0.f;

    const int nk = K >> 5;

#pragma unroll
    for (int s = 0; s < STAGES - 1; ++s) {
        uint32_t st = sbase + s * STAGE_BYTES;
        CP16(st + sA0, ag0 + s * 32);
        CP16(st + sA1, ag1 + s * 32);
        CP16(st + sB0, bg0 + s * 32);
        CP16(st + sB1, bg1 + s * 32);
        CP_COMMIT();
    }

    for (int t = 0; t < nk; ++t) {
        CP_WAIT(STAGES - 2);
        __syncthreads();
        const int tn = t + STAGES - 1;
        if (tn < nk) {
            uint32_t st = sbase + (tn & (STAGES - 1)) * STAGE_BYTES;
            CP16(st + sA0, ag0 + tn * 32);
            CP16(st + sA1, ag1 + tn * 32);
            CP16(st + sB0, bg0 + tn * 32);
            CP16(st + sB1, bg1 + tn * 32);
            CP_COMMIT();
        }
        const uint32_t* As_ = (const uint32_t*)(smem_raw + (t & (STAGES - 1)) * STAGE_BYTES);
        const uint32_t* Bs_ = As_ + 2560;
#pragma unroll
        for (int kb = 0; kb < 16; kb += 8) {
            uint32_t af[4][4], bf[4][2];
#pragma unroll
            for (int mt = 0; mt < 4; ++mt) {
                int base = (wm * 64 + mt * 16 + g) * 20 + kb + t4;
                af[mt][0] = As_[base];
                af[mt][1] = As_[base + 8 * 20];
                af[mt][2] = As_[base + 4];
                af[mt][3] = As_[base + 8 * 20 + 4];
            }
#pragma unroll
            for (int nt = 0; nt < 4; ++nt) {
                int nbase = (wn * 32 + nt * 8 + g) * 20 + kb + t4;
                bf[nt][0] = Bs_[nbase];
                bf[nt][1] = Bs_[nbase + 4];
            }
#pragma unroll
            for (int mt = 0; mt < 4; ++mt)
#pragma unroll
                for (int nt = 0; nt < 4; ++nt)
                    mma_f16(acc[mt][nt], af[mt], bf[nt]);
        }
    }

#pragma unroll
    for (int mt = 0; mt < 4; ++mt) {
        int r0 = brow + wm * 64 + mt * 16 + g;
#pragma unroll
        for (int nt = 0; nt < 4; ++nt) {
            int c0 = bcol + wn * 32 + nt * 8 + t4 * 2;
            float2 v0 = make_float2(acc[mt][nt][0], acc[mt][nt][1]);
            float2 v1 = make_float2(acc[mt][nt][2], acc[mt][nt][3]);
            if (OUT16) {
                __half* C16 = (__half*)Cv;
                *(uint32_t*)&C16[(size_t)r0 * ldc + c0]       = pack_h2(v0.x, v0.y);
                *(uint32_t*)&C16[(size_t)(r0 + 8) * ldc + c0] = pack_h2(v1.x, v1.y);
            } else {
                float* C = (float*)Cv;
                if (bias) {
                    float2 bv = *(const float2*)&bias[c0];
                    v0.x += bv.x; v0.y += bv.y; v1.x += bv.x; v1.y += bv.y;
                }
                if (res) {
                    float2 ra = *(const float2*)&res[(size_t)r0 * ldc + c0];
                    float2 rb = *(const float2*)&res[(size_t)(r0 + 8) * ldc + c0];
                    v0.x += ra.x; v0.y += ra.y; v1.x += rb.x; v1.y += rb.y;
                }
                *(float2*)&C[(size_t)r0 * ldc + c0]       = v0;
                *(float2*)&C[(size_t)(r0 + 8) * ldc + c0] = v1;
            }
        }
    }
}

__global__ __launch_bounds__(256, 2)
void gemm_f16(const __half* __restrict__ A, const __half* __restrict__ B,
              const float* __restrict__ bias, const float* __restrict__ res,
              float* __restrict__ C, int ldc, int K) {
    gemm_core<0>(A, B, bias, res, C, ldc, K);
}
__global__ __launch_bounds__(256, 2)
void gemm_f16_o16(const __half* __restrict__ A, const __half* __restrict__ B,
                  __half* __restrict__ C, int ldc, int K) {
    gemm_core<1>(A, B, nullptr, nullptr, C, ldc, K);
}

// ---------------- fp32 -> fp16 convert ----------------
__global__ void cvt16_kernel(const float* __restrict__ src, __half* __restrict__ dst, int n8) {
    int i = blockIdx.x * blockDim.x + threadIdx.x;
    if (i < n8) {
        float4 a = ((const float4*)src)[2 * i];
        float4 b = ((const float4*)src)[2 * i + 1];
        uint4 o;
        o.x = pack_h2(a.x, a.y); o.y = pack_h2(a.z, a.w);
        o.z = pack_h2(b.x, b.y); o.w = pack_h2(b.z, b.w);
        ((uint4*)dst)[i] = o;
    }
}

__global__ void pack_bias_kernel(const float* __restrict__ bq, const float* __restrict__ bk,
                                 const float* __restrict__ bv, float* __restrict__ dst) {
    int i = blockIdx.x * blockDim.x + threadIdx.x;
    if (i < QKV_LD)
        dst[i] = (i < 2048) ? bq[i] : ((i < 2560) ? bk[i - 2048] : bv[i - 2560]);
}

// ---------------- RMSNorm -> fp16 ----------------
__global__ void rmsnorm16_kernel(const float* __restrict__ x, const float* __restrict__ w,
                                 __half* __restrict__ out) {
    int row = blockIdx.x;
    const float* xr = x + (size_t)row * HIDN;
    float4 v[2];
    float ss = 0.f;
#pragma unroll
    for (int i = 0; i < 2; i++) {
        v[i] = *(const float4*)&xr[(threadIdx.x + i * 256) * 4];
        ss += v[i].x * v[i].x + v[i].y * v[i].y + v[i].z * v[i].z + v[i].w * v[i].w;
    }
#pragma unroll
    for (int o = 16; o; o >>= 1) ss += __shfl_xor_sync(~0u, ss, o);
    __shared__ float red[8];
    if ((threadIdx.x & 31) == 0) red[threadIdx.x >> 5] = ss;
    __syncthreads();
    if (threadIdx.x == 0) {
        float t = 0.f;
#pragma unroll
        for (int i = 0; i < 8; i++) t += red[i];
        red[0] = rsqrtf(t / (float)HIDN + EPSV);
    }
    __syncthreads();
    float r = red[0];
#pragma unroll
    for (int i = 0; i < 2; i++) {
        int c = (threadIdx.x + i * 256) * 4;
        float4 wv = *(const float4*)&w[c];
        uint2 o2;
        o2.x = pack_h2(v[i].x * r * wv.x, v[i].y * r * wv.y);
        o2.y = pack_h2(v[i].z * r * wv.z, v[i].w * r * wv.w);
        *(uint2*)&out[(size_t)row * HIDN + c] = o2;
    }
}

// ---------------- per-head RMSNorm + RoPE on packed qkv ----------------
__global__ void qknorm_rope_kernel(float* __restrict__ qkv,
                                   const float* __restrict__ qw, const float* __restrict__ kw,
                                   const float* __restrict__ cs, const float* __restrict__ sn) {
    int token = blockIdx.x, h = blockIdx.y;
    float* p; const float* w;
    if (h < NH) { p = qkv + (size_t)token * QKV_LD + h * HD;               w = qw; }
    else        { p = qkv + (size_t)token * QKV_LD + 2048 + (h - NH) * HD; w = kw; }
    int d = threadIdx.x;
    float v = p[d];
    float ss = v * v;
#pragma unroll
    for (int o = 16; o; o >>= 1) ss += __shfl_xor_sync(~0u, ss, o);
    __shared__ float red[4];
    __shared__ float sh[128];
    if ((d & 31) == 0) red[d >> 5] = ss;
    __syncthreads();
    float tot = red[0] + red[1] + red[2] + red[3];
    float r = rsqrtf(tot / 128.f + EPSV);
    float xn = v * r * w[d];
    sh[d] = xn;
    __syncthreads();
    float rot = (d < 64) ? -sh[d + 64] : sh[d - 64];
    float c = cs[(size_t)token * 128 + d], s = sn[(size_t)token * 128 + d];
    p[d] = xn * c + rot * s;
}

// ---------------- flash attention (fp16 MMA, causal, GQA) ----------------
// Tile 64(q) x 64(k), HD=128. 256 thr = 8 warps: 4(M) x 2(N).
// smem (u32): Qs[64][68] half2-packed along d; Ks[64][68]; Vs[32][136] packed
// along k (Vs[kk][d] = half2(V[2kk][d], V[2kk+1][d])); Ps[64][36].
#define AQK_STRIDE 68
#define AV_STRIDE  136
#define AP_STRIDE  36
#define ATTN_U32  (2 * 64 * AQK_STRIDE + 32 * AV_STRIDE + 64 * AP_STRIDE + 2*64 + 2*64 + 3*64)
#define ATTN_SMEM_BYTES (ATTN_U32 * 4)

__global__ __launch_bounds__(256, 2)
void attn_kernel(const float* __restrict__ qkv, __half* __restrict__ o16) {
    extern __shared__ uint32_t smem[];
    uint32_t* Qs = smem;
    uint32_t* Ks = Qs + 64 * AQK_STRIDE;
    uint32_t* Vs = Ks + 64 * AQK_STRIDE;
    uint32_t* Ps = Vs + 32 * AV_STRIDE;
    float* Pmax = (float*)(Ps + 64 * AP_STRIDE);
    float* Psum = Pmax + 128;
    float* Mrow = Psum + 128;
    float* Lrow = Mrow + 64;
    float* Arow = Lrow + 64;

    const int tid  = threadIdx.x;
    const int lane = tid & 31, warp = tid >> 5;
    const int wm = warp & 3, wn = warp >> 2;
    const int g = lane >> 2, t4 = lane & 3;
    const int qt = blockIdx.x, hq = blockIdx.y, b = blockIdx.z;
    const int kvh = hq >> 2;
    const int tok0 = b * SEQ + qt * 64;

    const int r0 = wm * 16 + g, r1 = r0 + 8;

    // load Q tile (scaled, fp16-packed)
    for (int l = tid; l < 64 * 32; l += 256) {
        int r = l >> 5, c = (l & 31);           // c: float4 chunk
        float4 qv = *(const float4*)&qkv[(size_t)(tok0 + r) * QKV_LD + hq * HD + c * 4];
        qv.x *= QK_SCALE; qv.y *= QK_SCALE; qv.z *= QK_SCALE; qv.w *= QK_SCALE;
        *(uint2*)&Qs[r * AQK_STRIDE + c * 2] = make_uint2(pack_h2(qv.x, qv.y), pack_h2(qv.z, qv.w));
    }
    if (tid < 64) { Mrow[tid] = -3.0e38f; Lrow[tid] = 0.f; }

    float O[8][4];
#pragma unroll
    for (int nt = 0; nt < 8; nt++)
#pragma unroll
        for (int e = 0; e < 4; e++) O[nt][e] = 0.f;
    __syncthreads();

    for (int kt = 0; kt <= qt; ++kt) {
        // K tile: row-major half2 along d
        for (int l = tid; l < 64 * 32; l += 256) {
            int r = l >> 5, c = (l & 31);
            float4 kv = *(const float4*)&qkv[(size_t)(b * SEQ + kt * 64 + r) * QKV_LD + 2048 + kvh * HD + c * 4];
            *(uint2*)&Ks[r * AQK_STRIDE + c * 2] = make_uint2(pack_h2(kv.x, kv.y), pack_h2(kv.z, kv.w));
        }
        // V tile: k-pair packed
        for (int l = tid; l < 32 * 32; l += 256) {
            int r = l >> 5, c = (l & 31);       // r: packed row (tokens 2r,2r+1)
            size_t base = (size_t)(b * SEQ + kt * 64 + 2 * r) * QKV_LD + 2560 + kvh * HD + c * 4;
            float4 va = *(const float4*)&qkv[base];
            float4 vb = *(const float4*)&qkv[base + QKV_LD];
            uint4 o4;
            o4.x = pack_h2(va.x, vb.x); o4.y = pack_h2(va.y, vb.y);
            o4.z = pack_h2(va.z, vb.z); o4.w = pack_h2(va.w, vb.w);
            *(uint4*)&Vs[r * AV_STRIDE + c * 4] = o4;
        }
        __syncthreads();

        // ---- S = Q K^T (fp16 MMA, warp tile 16 x 32) ----
        float s[4][4];
#pragma unroll
        for (int nt = 0; nt < 4; nt++)
#pragma unroll
            for (int e = 0; e < 4; e++) s[nt][e] = 0.f;
        {
            const int arow0 = r0 * AQK_STRIDE, arow1 = r1 * AQK_STRIDE;
#pragma unroll
            for (int kb = 0; kb < 64; kb += 8) {   // 8 chunks of k16
                uint32_t a[4];
                a[0] = Qs[arow0 + kb + t4];
                a[1] = Qs[arow1 + kb + t4];
                a[2] = Qs[arow0 + kb + t4 + 4];
                a[3] = Qs[arow1 + kb + t4 + 4];
#pragma unroll
                for (int nt = 0; nt < 4; nt++) {
                    uint32_t bb[2];
                    int nb = (wn * 32 + nt * 8 + g) * AQK_STRIDE + kb + t4;
                    bb[0] = Ks[nb]; bb[1] = Ks[nb + 4];
                    mma_f16(s[nt], a, bb);
                }
            }
        }

        if (kt == qt) {
#pragma unroll
            for (int nt = 0; nt < 4; nt++) {
                int c0 = wn * 32 + nt * 8 + 2 * t4;
                if (c0     > r0) s[nt][0] = -1.0e30f;
                if (c0 + 1 > r0) s[nt][1] = -1.0e30f;
                if (c0     > r1) s[nt][2] = -1.0e30f;
                if (c0 + 1 > r1) s[nt][3] = -1.0e30f;
            }
        }

        {
            float mx0 = fmaxf(fmaxf(s[0][0], s[0][1]), fmaxf(s[1][0], s[1][1]));
            mx0 = fmaxf(mx0, fmaxf(fmaxf(s[2][0], s[2][1]), fmaxf(s[3][0], s[3][1])));
            float mx1 = fmaxf(fmaxf(s[0][2], s[0][3]), fmaxf(s[1][2], s[1][3]));
            mx1 = fmaxf(mx1, fmaxf(fmaxf(s[2][2], s[2][3]), fmaxf(s[3][2], s[3][3])));
            mx0 = fmaxf(mx0, __shfl_xor_sync(~0u, mx0, 1));
            mx0 = fmaxf(mx0, __shfl_xor_sync(~0u, mx0, 2));
            mx1 = fmaxf(mx1, __shfl_xor_sync(~0u, mx1, 1));
            mx1 = fmaxf(mx1, __shfl_xor_sync(~0u, mx1, 2));
            if (t4 == 0) { Pmax[wn * 64 + r0] = mx0; Pmax[wn * 64 + r1] = mx1; }
        }
        __syncthreads();

        {
            float mn0 = fmaxf(Mrow[r0], fmaxf(Pmax[r0], Pmax[64 + r0]));
            float mn1 = fmaxf(Mrow[r1], fmaxf(Pmax[r1], Pmax[64 + r1]));
            float sum0 = 0.f, sum1 = 0.f;
#pragma unroll
            for (int nt = 0; nt < 4; nt++) {
                int cu = wn * 16 + nt * 4 + t4;    // u32 col in P
                float p0 = __expf(s[nt][0] - mn0);
                float p1 = __expf(s[nt][1] - mn0);
                float p2 = __expf(s[nt][2] - mn1);
                float p3 = __expf(s[nt][3] - mn1);
                sum0 += p0 + p1; sum1 += p2 + p3;
                Ps[r0 * AP_STRIDE + cu] = pack_h2(p0, p1);
                Ps[r1 * AP_STRIDE + cu] = pack_h2(p2, p3);
            }
            sum0 += __shfl_xor_sync(~0u, sum0, 1);
            sum0 += __shfl_xor_sync(~0u, sum0, 2);
            sum1 += __shfl_xor_sync(~0u, sum1, 1);
            sum1 += __shfl_xor_sync(~0u, sum1, 2);
            if (t4 == 0) { Psum[wn * 64 + r0] = sum0; Psum[wn * 64 + r1] = sum1; }
        }
        __syncthreads();

        if (tid < 64) {
            int r = tid;
            float mo = Mrow[r];
            float mn = fmaxf(mo, fmaxf(Pmax[r], Pmax[64 + r]));
            float al = __expf(mo - mn);
            Lrow[r] = Lrow[r] * al + Psum[r] + Psum[64 + r];
            Mrow[r] = mn;
            Arow[r] = al;
        }
        __syncthreads();

        // ---- O += P V (fp16 MMA, warp tile 16 x 64) ----
        {
            float al0 = Arow[r0], al1 = Arow[r1];
#pragma unroll
            for (int nt = 0; nt < 8; nt++) {
                O[nt][0] *= al0; O[nt][1] *= al0;
                O[nt][2] *= al1; O[nt][3] *= al1;
            }
            const int prow0 = r0 * AP_STRIDE, prow1 = r1 * AP_STRIDE;
#pragma unroll
            for (int kb = 0; kb < 32; kb += 8) {   // 4 chunks of k16
                uint32_t a[4];
                a[0] = Ps[prow0 + kb + t4];
                a[1] = Ps[prow1 + kb + t4];
                a[2] = Ps[prow0 + kb + t4 + 4];
                a[3] = Ps[prow1 + kb + t4 + 4];
#pragma unroll
                for (int nt = 0; nt < 8; nt++) {
                    uint32_t bb[2];
                    int col = wn * 64 + nt * 8 + g;
                    bb[0] = Vs[(kb + t4) * AV_STRIDE + col];
                    bb[1] = Vs[(kb + t4 + 4) * AV_STRIDE + col];
                    mma_f16(O[nt], a, bb);
                }
            }
        }
        __syncthreads();
    }

    {
        float inv0 = 1.f / Lrow[r0], inv1 = 1.f / Lrow[r1];
        size_t base0 = (size_t)(tok0 + r0) * (NH * HD) + hq * HD;
        size_t base1 = (size_t)(tok0 + r1) * (NH * HD) + hq * HD;
#pragma unroll
        for (int nt = 0; nt < 8; nt++) {
            int c = wn * 64 + nt * 8 + 2 * t4;
            *(uint32_t*)&o16[base0 + c] = pack_h2(O[nt][0] * inv0, O[nt][1] * inv0);
            *(uint32_t*)&o16[base1 + c] = pack_h2(O[nt][2] * inv1, O[nt][3] * inv1);
        }
    }
}

// ---------------- silu(gate)*up (fp16 in/out) ----------------
__global__ void silu16_kernel(const __half* __restrict__ gu, __half* __restrict__ act, int n8) {
    int i = blockIdx.x * blockDim.x + threadIdx.x;
    if (i >= n8) return;
    int r = i >> 10;                 // INTER/8 = 1024 chunks per row
    int c8 = (i & 1023) * 8;
    const __half* gp = gu + (size_t)r * (2 * INTERN) + c8;
    const __half* up = gp + INTERN;
    uint4 gx = *(const uint4*)gp;
    uint4 ux = *(const uint4*)up;
    float2 g0 = unpack_h2(gx.x), g1 = unpack_h2(gx.y), g2 = unpack_h2(gx.z), g3 = unpack_h2(gx.w);
    float2 u0 = unpack_h2(ux.x), u1 = unpack_h2(ux.y), u2 = unpack_h2(ux.z), u3 = unpack_h2(ux.w);
    g0.x = g0.x / (1.f + __expf(-g0.x)) * u0.x;
    g0.y = g0.y / (1.f + __expf(-g0.y)) * u0.y;
    g1.x = g1.x / (1.f + __expf(-g1.x)) * u1.x;
    g1.y = g1.y / (1.f + __expf(-g1.y)) * u1.y;
    g2.x = g2.x / (1.f + __expf(-g2.x)) * u2.x;
    g2.y = g2.y / (1.f + __expf(-g2.y)) * u2.y;
    g3.x = g3.x / (1.f + __expf(-g3.x)) * u3.x;
    g3.y = g3.y / (1.f + __expf(-g3.y)) * u3.y;
    uint4 o;
    o.x = pack_h2(g0.x, g0.y); o.y = pack_h2(g1.x, g1.y);
    o.z = pack_h2(g2.x, g2.y); o.w = pack_h2(g3.x, g3.y);
    ((uint4*)act)[i] = o;
}

// ---------------- host orchestration ----------------
extern "C" void kernel_launch(void* const* d_in, const int* in_sizes, int n_in,
                              void* d_out, int out_size) {
    const float* x    = (const float*)d_in[0];
    const float* cosb = (const float*)d_in[2];
    const float* sinb = (const float*)d_in[3];
    const float* wq   = (const float*)d_in[4];
    const float* bq   = (const float*)d_in[5];
    const float* wk   = (const float*)d_in[6];
    const float* bk   = (const float*)d_in[7];
    const float* wv   = (const float*)d_in[8];
    const float* bv   = (const float*)d_in[9];
    const float* wo   = (const float*)d_in[10];
    const float* qnw  = (const float*)d_in[11];
    const float* knw  = (const float*)d_in[12];
    const float* ln1  = (const float*)d_in[13];
    const float* ln2  = (const float*)d_in[14];
    const float* wg   = (const float*)d_in[15];
    const float* wu   = (const float*)d_in[16];
    const float* wd   = (const float*)d_in[17];
    float* out = (float*)d_out;

    __half *h16, *attn16, *act16, *wqkv16, *wo16, *wgu16, *wd16, *gu16;
    float *qkv_, *x1_, *bqkv;
    cudaGetSymbolAddress((void**)&h16,    g_h16);
    cudaGetSymbolAddress((void**)&attn16, g_attn16);
    cudaGetSymbolAddress((void**)&act16,  g_act16);
    cudaGetSymbolAddress((void**)&wqkv16, g_wqkv16);
    cudaGetSymbolAddress((void**)&wo16,   g_wo16);
    cudaGetSymbolAddress((void**)&wgu16,  g_wgu16);
    cudaGetSymbolAddress((void**)&wd16,   g_wd16);
    cudaGetSymbolAddress((void**)&gu16,   g_gu16);
    cudaGetSymbolAddress((void**)&qkv_,   g_qkv);
    cudaGetSymbolAddress((void**)&x1_,    g_x1);
    cudaGetSymbolAddress((void**)&bqkv,   g_bqkv);

    cudaFuncSetAttribute(attn_kernel,  cudaFuncAttributeMaxDynamicSharedMemorySize, ATTN_SMEM_BYTES);
    cudaFuncSetAttribute(gemm_f16,     cudaFuncAttributeMaxDynamicSharedMemorySize, GEMM_SMEM_BYTES);
    cudaFuncSetAttribute(gemm_f16_o16, cudaFuncAttributeMaxDynamicSharedMemorySize, GEMM_SMEM_BYTES);

    // 0. weight conversion / packing
    {
        const int T = 256;
        cvt16_kernel<<<(2048*2048/8 + T-1)/T, T>>>(wq, wqkv16,                 2048*2048/8);
        cvt16_kernel<<<( 512*2048/8 + T-1)/T, T>>>(wk, wqkv16 + 2048*2048,      512*2048/8);
        cvt16_kernel<<<( 512*2048/8 + T-1)/T, T>>>(wv, wqkv16 + 2560*2048,      512*2048/8);
        cvt16_kernel<<<(2048*2048/8 + T-1)/T, T>>>(wo, wo16,                   2048*2048/8);
        cvt16_kernel<<<(8192*2048/8 + T-1)/T, T>>>(wg, wgu16,                  8192*2048/8);
        cvt16_kernel<<<(8192*2048/8 + T-1)/T, T>>>(wu, wgu16 + 8192*2048,      8192*2048/8);
        cvt16_kernel<<<(2048*8192/8 + T-1)/T, T>>>(wd, wd16,                   2048*8192/8);
        pack_bias_kernel<<<(QKV_LD + T-1)/T, T>>>(bq, bk, bv, bqkv);
    }

    // 1. h16 = (half) RMSNorm(x, ln1)
    rmsnorm16_kernel<<<TTOK, 256>>>(x, ln1, h16);
    // 2. packed QKV projection
    gemm_f16<<<dim3(QKV_LD/128, TTOK/128), 256, GEMM_SMEM_BYTES>>>(h16, wqkv16, bqkv, nullptr, qkv_, QKV_LD, HIDN);
    // 3. per-head RMSNorm + RoPE (in place, packed)
    qknorm_rope_kernel<<<dim3(TTOK, NH + NKV), 128>>>(qkv_, qnw, knw, cosb, sinb);
    // 4. causal flash attention (fp16 MMA) -> fp16
    attn_kernel<<<dim3(SEQ/64, NH, BATCH), 256, ATTN_SMEM_BYTES>>>(qkv_, attn16);
    // 5. x1 = x + attn @ wo^T
    gemm_f16<<<dim3(HIDN/128, TTOK/128), 256, GEMM_SMEM_BYTES>>>(attn16, wo16, nullptr, x, x1_, HIDN, HIDN);
    // 6. h16 = (half) RMSNorm(x1, ln2)
    rmsnorm16_kernel<<<TTOK, 256>>>(x1_, ln2, h16);
    // 7. gate|up projection -> fp16
    gemm_f16_o16<<<dim3(2*INTERN/128, TTOK/128), 256, GEMM_SMEM_BYTES>>>(h16, wgu16, gu16, 2*INTERN, HIDN);
    // 8. act16 = (half)(silu(gate) * up)
    silu16_kernel<<<TTOK*INTERN/8/256, 256>>>(gu16, act16, TTOK*INTERN/8);
    // 9. out = x1 + act @ wd^T
    gemm_f16<<<dim3(HIDN/128, TTOK/128), 256, GEMM_SMEM_BYTES>>>(act16, wd16, nullptr, x1_, out, HIDN, INTERN);
}

// round 11
// speedup vs baseline: 2.0011x; 1.0006x over previous
#include <cuda_runtime.h>
#include <cuda_fp16.h>
#include <cstdint>

#define HIDN   2048
#define NH     16
#define NKV    4
#define HD     128
#define INTERN 8192
#define BATCH  4
#define SEQ    1024
#define TTOK   (BATCH*SEQ)   /* 4096 */
#define EPSV   1e-6f
#define QK_SCALE 0.08838834764831845f  /* 1/sqrt(128) */
#define QKV_LD (NH*HD + 2*NKV*HD)      /* 3072 */

// ---------------- scratch ----------------
__device__ __half g_h16   [TTOK * HIDN];
__device__ float  g_qkv   [TTOK * QKV_LD];
__device__ __half g_attn16[TTOK * HIDN];
__device__ float  g_x1    [TTOK * HIDN];
__device__ __half g_gu16  [TTOK * 2 * INTERN];
__device__ __half g_act16 [TTOK * INTERN];
// fp16 weights
__device__ __half g_wqkv16[QKV_LD * HIDN];
__device__ __half g_wo16  [HIDN * HIDN];
__device__ __half g_wgu16 [2 * INTERN * HIDN];
__device__ __half g_wd16  [HIDN * INTERN];
__device__ float  g_bqkv  [QKV_LD];

// ---------------- helpers ----------------
__device__ __forceinline__ void mma_f16(float c[4], const uint32_t a[4], const uint32_t b[2]) {
    asm volatile("mma.sync.aligned.m16n8k16.row.col.f32.f16.f16.f32 "
        "{%0,%1,%2,%3}, {%4,%5,%6,%7}, {%8,%9}, {%0,%1,%2,%3};\n"
        : "+f"(c[0]), "+f"(c[1]), "+f"(c[2]), "+f"(c[3])
        : "r"(a[0]), "r"(a[1]), "r"(a[2]), "r"(a[3]), "r"(b[0]), "r"(b[1]));
}
__device__ __forceinline__ uint32_t pack_h2(float lo, float hi) {
    __half2 h = __floats2half2_rn(lo, hi);
    return *(uint32_t*)&h;
}
__device__ __forceinline__ float2 unpack_h2(uint32_t u) {
    return __half22float2(*(__half2*)&u);
}

#define CP16(dst, src) \
    asm volatile("cp.async.cg.shared.global [%0], [%1], 16;" :: "r"(dst), "l"(src))
#define CP_COMMIT() asm volatile("cp.async.commit_group;")
#define CP_WAIT(n)  asm volatile("cp.async.wait_group %0;" :: "n"(n))

// ---------------- fp16 GEMM with cp.async 4-stage pipeline ----------------
// C[M,ldc] = A[M,K](fp16) @ B[N,K]^T(fp16) (+bias)(+res).
// BM=BN=128, BK=32. 256 thr, 8 warps (2M x 4N), warp tile 64x32.
#define STAGES 4
#define STAGE_BYTES 20480
#define GEMM_SMEM_BYTES (STAGES * STAGE_BYTES)   /* 81920 */

// OUT16=0: float C; OUT16=1: half C (no bias/res)
template<int OUT16>
__device__ __forceinline__ void gemm_core(
    const __half* __restrict__ A, const __half* __restrict__ B,
    const float* __restrict__ bias, const float* __restrict__ res,
    void* __restrict__ Cv, int ldc, int K)
{
    extern __shared__ uint8_t smem_raw[];
    const int tid  = threadIdx.x;
    const int lane = tid & 31, warp = tid >> 5;
    const int wm = warp & 1, wn = warp >> 1;
    const int g  = lane >> 2, t4 = lane & 3;
    const int brow = blockIdx.y << 7, bcol = blockIdx.x << 7;

    const int ar = tid >> 2, achk = tid & 3;
    const __half* ag0 = A + (size_t)(brow + ar) * K + achk * 8;
    const __half* ag1 = ag0 + (size_t)64 * K;
    const __half* bg0 = B + (size_t)(bcol + ar) * K + achk * 8;
    const __half* bg1 = bg0 + (size_t)64 * K;

    const uint32_t sbase = (uint32_t)__cvta_generic_to_shared(smem_raw);
    const uint32_t sA0 = ar * 80 + achk * 16;
    const uint32_t sA1 = sA0 + 64 * 80;
    const uint32_t sB0 = 10240 + sA0;
    const uint32_t sB1 = 10240 + sA1;

    float acc[4][4][4];
#pragma unroll
    for (int i = 0; i < 4; i++)
#pragma unroll
        for (int j = 0; j < 4; j++)
#pragma unroll
            for (int e = 0; e < 4; e++) acc[i][j][e] = 0.f;

    const int nk = K >> 5;

#pragma unroll
    for (int s = 0; s < STAGES - 1; ++s) {
        uint32_t st = sbase + s * STAGE_BYTES;
        CP16(st + sA0, ag0 + s * 32);
        CP16(st + sA1, ag1 + s * 32);
        CP16(st + sB0, bg0 + s * 32);
        CP16(st + sB1, bg1 + s * 32);
        CP_COMMIT();
    }

    for (int t = 0; t < nk; ++t) {
        CP_WAIT(STAGES - 2);
        __syncthreads();
        const int tn = t + STAGES - 1;
        if (tn < nk) {
            uint32_t st = sbase + (tn & (STAGES - 1)) * STAGE_BYTES;
            CP16(st + sA0, ag0 + tn * 32);
            CP16(st + sA1, ag1 + tn * 32);
            CP16(st + sB0, bg0 + tn * 32);
            CP16(st + sB1, bg1 + tn * 32);
            CP_COMMIT();
        }
        const uint32_t* As_ = (const uint32_t*)(smem_raw + (t & (STAGES - 1)) * STAGE_BYTES);
        const uint32_t* Bs_ = As_ + 2560;
#pragma unroll
        for (int kb = 0; kb < 16; kb += 8) {
            uint32_t af[4][4], bf[4][2];
#pragma unroll
            for (int mt = 0; mt < 4; ++mt) {
                int base = (wm * 64 + mt * 16 + g) * 20 + kb + t4;
                af[mt][0] = As_[base];
                af[mt][1] = As_[base + 8 * 20];
                af[mt][2] = As_[base + 4];
                af[mt][3] = As_[base + 8 * 20 + 4];
            }
#pragma unroll
            for (int nt = 0; nt < 4; ++nt) {
                int nbase = (wn * 32 + nt * 8 + g) * 20 + kb + t4;
                bf[nt][0] = Bs_[nbase];
                bf[nt][1] = Bs_[nbase + 4];
            }
#pragma unroll
            for (int mt = 0; mt < 4; ++mt)
#pragma unroll
                for (int nt = 0; nt < 4; ++nt)
                    mma_f16(acc[mt][nt], af[mt], bf[nt]);
        }
    }

#pragma unroll
    for (int mt = 0; mt < 4; ++mt) {
        int r0 = brow + wm * 64 + mt * 16 + g;
#pragma unroll
        for (int nt = 0; nt < 4; ++nt) {
            int c0 = bcol + wn * 32 + nt * 8 + t4 * 2;
            float2 v0 = make_float2(acc[mt][nt][0], acc[mt][nt][1]);
            float2 v1 = make_float2(acc[mt][nt][2], acc[mt][nt][3]);
            if (OUT16) {
                __half* C16 = (__half*)Cv;
                *(uint32_t*)&C16[(size_t)r0 * ldc + c0]       = pack_h2(v0.x, v0.y);
                *(uint32_t*)&C16[(size_t)(r0 + 8) * ldc + c0] = pack_h2(v1.x, v1.y);
            } else {
                float* C = (float*)Cv;
                if (bias) {
                    float2 bv = *(const float2*)&bias[c0];
                    v0.x += bv.x; v0.y += bv.y; v1.x += bv.x; v1.y += bv.y;
                }
                if (res) {
                    float2 ra = *(const float2*)&res[(size_t)r0 * ldc + c0];
                    float2 rb = *(const float2*)&res[(size_t)(r0 + 8) * ldc + c0];
                    v0.x += ra.x; v0.y += ra.y; v1.x += rb.x; v1.y += rb.y;
                }
                *(float2*)&C[(size_t)r0 * ldc + c0]       = v0;
                *(float2*)&C[(size_t)(r0 + 8) * ldc + c0] = v1;
            }
        }
    }
}

__global__ __launch_bounds__(256, 2)
void gemm_f16(const __half* __restrict__ A, const __half* __restrict__ B,
              const float* __restrict__ bias, const float* __restrict__ res,
              float* __restrict__ C, int ldc, int K) {
    gemm_core<0>(A, B, bias, res, C, ldc, K);
}
__global__ __launch_bounds__(256, 2)
void gemm_f16_o16(const __half* __restrict__ A, const __half* __restrict__ B,
                  __half* __restrict__ C, int ldc, int K) {
    gemm_core<1>(A, B, nullptr, nullptr, C, ldc, K);
}

// ---------------- fp32 -> fp16 convert ----------------
__global__ void cvt16_kernel(const float* __restrict__ src, __half* __restrict__ dst, int n8) {
    int i = blockIdx.x * blockDim.x + threadIdx.x;
    if (i < n8) {
        float4 a = ((const float4*)src)[2 * i];
        float4 b = ((const float4*)src)[2 * i + 1];
        uint4 o;
        o.x = pack_h2(a.x, a.y); o.y = pack_h2(a.z, a.w);
        o.z = pack_h2(b.x, b.y); o.w = pack_h2(b.z, b.w);
        ((uint4*)dst)[i] = o;
    }
}

__global__ void pack_bias_kernel(const float* __restrict__ bq, const float* __restrict__ bk,
                                 const float* __restrict__ bv, float* __restrict__ dst) {
    int i = blockIdx.x * blockDim.x + threadIdx.x;
    if (i < QKV_LD)
        dst[i] = (i < 2048) ? bq[i] : ((i < 2560) ? bk[i - 2048] : bv[i - 2560]);
}

// ---------------- RMSNorm -> fp16 ----------------
__global__ void rmsnorm16_kernel(const float* __restrict__ x, const float* __restrict__ w,
                                 __half* __restrict__ out) {
    int row = blockIdx.x;
    const float* xr = x + (size_t)row * HIDN;
    float4 v[2];
    float ss = 0.f;
#pragma unroll
    for (int i = 0; i < 2; i++) {
        v[i] = *(const float4*)&xr[(threadIdx.x + i * 256) * 4];
        ss += v[i].x * v[i].x + v[i].y * v[i].y + v[i].z * v[i].z + v[i].w * v[i].w;
    }
#pragma unroll
    for (int o = 16; o; o >>= 1) ss += __shfl_xor_sync(~0u, ss, o);
    __shared__ float red[8];
    if ((threadIdx.x & 31) == 0) red[threadIdx.x >> 5] = ss;
    __syncthreads();
    if (threadIdx.x == 0) {
        float t = 0.f;
#pragma unroll
        for (int i = 0; i < 8; i++) t += red[i];
        red[0] = rsqrtf(t / (float)HIDN + EPSV);
    }
    __syncthreads();
    float r = red[0];
#pragma unroll
    for (int i = 0; i < 2; i++) {
        int c = (threadIdx.x + i * 256) * 4;
        float4 wv = *(const float4*)&w[c];
        uint2 o2;
        o2.x = pack_h2(v[i].x * r * wv.x, v[i].y * r * wv.y);
        o2.y = pack_h2(v[i].z * r * wv.z, v[i].w * r * wv.w);
        *(uint2*)&out[(size_t)row * HIDN + c] = o2;
    }
}

// ---------------- per-head RMSNorm + RoPE on packed qkv ----------------
__global__ void qknorm_rope_kernel(float* __restrict__ qkv,
                                   const float* __restrict__ qw, const float* __restrict__ kw,
                                   const float* __restrict__ cs, const float* __restrict__ sn) {
    int token = blockIdx.x, h = blockIdx.y;
    float* p; const float* w;
    if (h < NH) { p = qkv + (size_t)token * QKV_LD + h * HD;               w = qw; }
    else        { p = qkv + (size_t)token * QKV_LD + 2048 + (h - NH) * HD; w = kw; }
    int d = threadIdx.x;
    float v = p[d];
    float ss = v * v;
#pragma unroll
    for (int o = 16; o; o >>= 1) ss += __shfl_xor_sync(~0u, ss, o);
    __shared__ float red[4];
    __shared__ float sh[128];
    if ((d & 31) == 0) red[d >> 5] = ss;
    __syncthreads();
    float tot = red[0] + red[1] + red[2] + red[3];
    float r = rsqrtf(tot / 128.f + EPSV);
    float xn = v * r * w[d];
    sh[d] = xn;
    __syncthreads();
    float rot = (d < 64) ? -sh[d + 64] : sh[d - 64];
    float c = cs[(size_t)token * 128 + d], s = sn[(size_t)token * 128 + d];
    p[d] = xn * c + rot * s;
}

// ---------------- flash attention (fp16 MMA, causal, GQA) ----------------
// Tile 64(q) x 64(k), HD=128. 256 thr = 8 warps: 4(M) x 2(N).
// smem (u32): Qs[64][68] half2-packed along d; Ks[64][68]; Vs[32][136] packed
// along k (Vs[kk][d] = half2(V[2kk][d], V[2kk+1][d])); Ps[64][36].
#define AQK_STRIDE 68
#define AV_STRIDE  136
#define AP_STRIDE  36
#define ATTN_U32  (2 * 64 * AQK_STRIDE + 32 * AV_STRIDE + 64 * AP_STRIDE + 2*64 + 2*64 + 3*64)
#define ATTN_SMEM_BYTES (ATTN_U32 * 4)

__global__ __launch_bounds__(256, 2)
void attn_kernel(const float* __restrict__ qkv, __half* __restrict__ o16) {
    extern __shared__ uint32_t smem[];
    uint32_t* Qs = smem;
    uint32_t* Ks = Qs + 64 * AQK_STRIDE;
    uint32_t* Vs = Ks + 64 * AQK_STRIDE;
    uint32_t* Ps = Vs + 32 * AV_STRIDE;
    float* Pmax = (float*)(Ps + 64 * AP_STRIDE);
    float* Psum = Pmax + 128;
    float* Mrow = Psum + 128;
    float* Lrow = Mrow + 64;
    float* Arow = Lrow + 64;

    const int tid  = threadIdx.x;
    const int lane = tid & 31, warp = tid >> 5;
    const int wm = warp & 3, wn = warp >> 2;
    const int g = lane >> 2, t4 = lane & 3;
    const int qt = blockIdx.x, hq = blockIdx.y, b = blockIdx.z;
    const int kvh = hq >> 2;
    const int tok0 = b * SEQ + qt * 64;

    const int r0 = wm * 16 + g, r1 = r0 + 8;

    // load Q tile (scaled, fp16-packed)
    for (int l = tid; l < 64 * 32; l += 256) {
        int r = l >> 5, c = (l & 31);           // c: float4 chunk
        float4 qv = *(const float4*)&qkv[(size_t)(tok0 + r) * QKV_LD + hq * HD + c * 4];
        qv.x *= QK_SCALE; qv.y *= QK_SCALE; qv.z *= QK_SCALE; qv.w *= QK_SCALE;
        *(uint2*)&Qs[r * AQK_STRIDE + c * 2] = make_uint2(pack_h2(qv.x, qv.y), pack_h2(qv.z, qv.w));
    }
    if (tid < 64) { Mrow[tid] = -3.0e38f; Lrow[tid] = 0.f; }

    float O[8][4];
#pragma unroll
    for (int nt = 0; nt < 8; nt++)
#pragma unroll
        for (int e = 0; e < 4; e++) O[nt][e] = 0.f;
    __syncthreads();

    for (int kt = 0; kt <= qt; ++kt) {
        // K tile: row-major half2 along d
        for (int l = tid; l < 64 * 32; l += 256) {
            int r = l >> 5, c = (l & 31);
            float4 kv = *(const float4*)&qkv[(size_t)(b * SEQ + kt * 64 + r) * QKV_LD + 2048 + kvh * HD + c * 4];
            *(uint2*)&Ks[r * AQK_STRIDE + c * 2] = make_uint2(pack_h2(kv.x, kv.y), pack_h2(kv.z, kv.w));
        }
        // V tile: k-pair packed
        for (int l = tid; l < 32 * 32; l += 256) {
            int r = l >> 5, c = (l & 31);       // r: packed row (tokens 2r,2r+1)
            size_t base = (size_t)(b * SEQ + kt * 64 + 2 * r) * QKV_LD + 2560 + kvh * HD + c * 4;
            float4 va = *(const float4*)&qkv[base];
            float4 vb = *(const float4*)&qkv[base + QKV_LD];
            uint4 o4;
            o4.x = pack_h2(va.x, vb.x); o4.y = pack_h2(va.y, vb.y);
            o4.z = pack_h2(va.z, vb.z); o4.w = pack_h2(va.w, vb.w);
            *(uint4*)&Vs[r * AV_STRIDE + c * 4] = o4;
        }
        __syncthreads();

        // ---- S = Q K^T (fp16 MMA, warp tile 16 x 32) ----
        float s[4][4];
#pragma unroll
        for (int nt = 0; nt < 4; nt++)
#pragma unroll
            for (int e = 0; e < 4; e++) s[nt][e] = 0.f;
        {
            const int arow0 = r0 * AQK_STRIDE, arow1 = r1 * AQK_STRIDE;
#pragma unroll
            for (int kb = 0; kb < 64; kb += 8) {   // 8 chunks of k16
                uint32_t a[4];
                a[0] = Qs[arow0 + kb + t4];
                a[1] = Qs[arow1 + kb + t4];
                a[2] = Qs[arow0 + kb + t4 + 4];
                a[3] = Qs[arow1 + kb + t4 + 4];
#pragma unroll
                for (int nt = 0; nt < 4; nt++) {
                    uint32_t bb[2];
                    int nb = (wn * 32 + nt * 8 + g) * AQK_STRIDE + kb + t4;
                    bb[0] = Ks[nb]; bb[1] = Ks[nb + 4];
                    mma_f16(s[nt], a, bb);
                }
            }
        }

        if (kt == qt) {
#pragma unroll
            for (int nt = 0; nt < 4; nt++) {
                int c0 = wn * 32 + nt * 8 + 2 * t4;
                if (c0     > r0) s[nt][0] = -1.0e30f;
                if (c0 + 1 > r0) s[nt][1] = -1.0e30f;
                if (c0     > r1) s[nt][2] = -1.0e30f;
                if (c0 + 1 > r1) s[nt][3] = -1.0e30f;
            }
        }

        {
            float mx0 = fmaxf(fmaxf(s[0][0], s[0][1]), fmaxf(s[1][0], s[1][1]));
            mx0 = fmaxf(mx0, fmaxf(fmaxf(s[2][0], s[2][1]), fmaxf(s[3][0], s[3][1])));
            float mx1 = fmaxf(fmaxf(s[0][2], s[0][3]), fmaxf(s[1][2], s[1][3]));
            mx1 = fmaxf(mx1, fmaxf(fmaxf(s[2][2], s[2][3]), fmaxf(s[3][2], s[3][3])));
            mx0 = fmaxf(mx0, __shfl_xor_sync(~0u, mx0, 1));
            mx0 = fmaxf(mx0, __shfl_xor_sync(~0u, mx0, 2));
            mx1 = fmaxf(mx1, __shfl_xor_sync(~0u, mx1, 1));
            mx1 = fmaxf(mx1, __shfl_xor_sync(~0u, mx1, 2));
            if (t4 == 0) { Pmax[wn * 64 + r0] = mx0; Pmax[wn * 64 + r1] = mx1; }
        }
        __syncthreads();

        {
            float mn0 = fmaxf(Mrow[r0], fmaxf(Pmax[r0], Pmax[64 + r0]));
            float mn1 = fmaxf(Mrow[r1], fmaxf(Pmax[r1], Pmax[64 + r1]));
            float sum0 = 0.f, sum1 = 0.f;
#pragma unroll
            for (int nt = 0; nt < 4; nt++) {
                int cu = wn * 16 + nt * 4 + t4;    // u32 col in P
                float p0 = __expf(s[nt][0] - mn0);
                float p1 = __expf(s[nt][1] - mn0);
                float p2 = __expf(s[nt][2] - mn1);
                float p3 = __expf(s[nt][3] - mn1);
                sum0 += p0 + p1; sum1 += p2 + p3;
                Ps[r0 * AP_STRIDE + cu] = pack_h2(p0, p1);
                Ps[r1 * AP_STRIDE + cu] = pack_h2(p2, p3);
            }
            sum0 += __shfl_xor_sync(~0u, sum0, 1);
            sum0 += __shfl_xor_sync(~0u, sum0, 2);
            sum1 += __shfl_xor_sync(~0u, sum1, 1);
            sum1 += __shfl_xor_sync(~0u, sum1, 2);
            if (t4 == 0) { Psum[wn * 64 + r0] = sum0; Psum[wn * 64 + r1] = sum1; }
        }
        __syncthreads();

        if (tid < 64) {
            int r = tid;
            float mo = Mrow[r];
            float mn = fmaxf(mo, fmaxf(Pmax[r], Pmax[64 + r]));
            float al = __expf(mo - mn);
            Lrow[r] = Lrow[r] * al + Psum[r] + Psum[64 + r];
            Mrow[r] = mn;
            Arow[r] = al;
        }
        __syncthreads();

        // ---- O += P V (fp16 MMA, warp tile 16 x 64) ----
        {
            float al0 = Arow[r0], al1 = Arow[r1];
#pragma unroll
            for (int nt = 0; nt < 8; nt++) {
                O[nt][0] *= al0; O[nt][1] *= al0;
                O[nt][2] *= al1; O[nt][3] *= al1;
            }
            const int prow0 = r0 * AP_STRIDE, prow1 = r1 * AP_STRIDE;
#pragma unroll
            for (int kb = 0; kb < 32; kb += 8) {   // 4 chunks of k16
                uint32_t a[4];
                a[0] = Ps[prow0 + kb + t4];
                a[1] = Ps[prow1 + kb + t4];
                a[2] = Ps[prow0 + kb + t4 + 4];
                a[3] = Ps[prow1 + kb + t4 + 4];
#pragma unroll
                for (int nt = 0; nt < 8; nt++) {
                    uint32_t bb[2];
                    int col = wn * 64 + nt * 8 + g;
                    bb[0] = Vs[(kb + t4) * AV_STRIDE + col];
                    bb[1] = Vs[(kb + t4 + 4) * AV_STRIDE + col];
                    mma_f16(O[nt], a, bb);
                }
            }
        }
        __syncthreads();
    }

    {
        float inv0 = 1.f / Lrow[r0], inv1 = 1.f / Lrow[r1];
        size_t base0 = (size_t)(tok0 + r0) * (NH * HD) + hq * HD;
        size_t base1 = (size_t)(tok0 + r1) * (NH * HD) + hq * HD;
#pragma unroll
        for (int nt = 0; nt < 8; nt++) {
            int c = wn * 64 + nt * 8 + 2 * t4;
            *(uint32_t*)&o16[base0 + c] = pack_h2(O[nt][0] * inv0, O[nt][1] * inv0);
            *(uint32_t*)&o16[base1 + c] = pack_h2(O[nt][2] * inv1, O[nt][3] * inv1);
        }
    }
}

// ---------------- silu(gate)*up (fp16 in/out) ----------------
__global__ void silu16_kernel(const __half* __restrict__ gu, __half* __restrict__ act, int n8) {
    int i = blockIdx.x * blockDim.x + threadIdx.x;
    if (i >= n8) return;
    int r = i >> 10;                 // INTER/8 = 1024 chunks per row
    int c8 = (i & 1023) * 8;
    const __half* gp = gu + (size_t)r * (2 * INTERN) + c8;
    const __half* up = gp + INTERN;
    uint4 gx = *(const uint4*)gp;
    uint4 ux = *(const uint4*)up;
    float2 g0 = unpack_h2(gx.x), g1 = unpack_h2(gx.y), g2 = unpack_h2(gx.z), g3 = unpack_h2(gx.w);
    float2 u0 = unpack_h2(ux.x), u1 = unpack_h2(ux.y), u2 = unpack_h2(ux.z), u3 = unpack_h2(ux.w);
    g0.x = g0.x / (1.f + __expf(-g0.x)) * u0.x;
    g0.y = g0.y / (1.f + __expf(-g0.y)) * u0.y;
    g1.x = g1.x / (1.f + __expf(-g1.x)) * u1.x;
    g1.y = g1.y / (1.f + __expf(-g1.y)) * u1.y;
    g2.x = g2.x / (1.f + __expf(-g2.x)) * u2.x;
    g2.y = g2.y / (1.f + __expf(-g2.y)) * u2.y;
    g3.x = g3.x / (1.f + __expf(-g3.x)) * u3.x;
    g3.y = g3.y / (1.f + __expf(-g3.y)) * u3.y;
    uint4 o;
    o.x = pack_h2(g0.x, g0.y); o.y = pack_h2(g1.x, g1.y);
    o.z = pack_h2(g2.x, g2.y); o.w = pack_h2(g3.x, g3.y);
    ((uint4*)act)[i] = o;
}

// ---------------- host orchestration ----------------
extern "C" void kernel_launch(void* const* d_in, const int* in_sizes, int n_in,
                              void* d_out, int out_size) {
    const float* x    = (const float*)d_in[0];
    const float* cosb = (const float*)d_in[2];
    const float* sinb = (const float*)d_in[3];
    const float* wq   = (const float*)d_in[4];
    const float* bq   = (const float*)d_in[5];
    const float* wk   = (const float*)d_in[6];
    const float* bk   = (const float*)d_in[7];
    const float* wv   = (const float*)d_in[8];
    const float* bv   = (const float*)d_in[9];
    const float* wo   = (const float*)d_in[10];
    const float* qnw  = (const float*)d_in[11];
    const float* knw  = (const float*)d_in[12];
    const float* ln1  = (const float*)d_in[13];
    const float* ln2  = (const float*)d_in[14];
    const float* wg   = (const float*)d_in[15];
    const float* wu   = (const float*)d_in[16];
    const float* wd   = (const float*)d_in[17];
    float* out = (float*)d_out;

    __half *h16, *attn16, *act16, *wqkv16, *wo16, *wgu16, *wd16, *gu16;
    float *qkv_, *x1_, *bqkv;
    cudaGetSymbolAddress((void**)&h16,    g_h16);
    cudaGetSymbolAddress((void**)&attn16, g_attn16);
    cudaGetSymbolAddress((void**)&act16,  g_act16);
    cudaGetSymbolAddress((void**)&wqkv16, g_wqkv16);
    cudaGetSymbolAddress((void**)&wo16,   g_wo16);
    cudaGetSymbolAddress((void**)&wgu16,  g_wgu16);
    cudaGetSymbolAddress((void**)&wd16,   g_wd16);
    cudaGetSymbolAddress((void**)&gu16,   g_gu16);
    cudaGetSymbolAddress((void**)&qkv_,   g_qkv);
    cudaGetSymbolAddress((void**)&x1_,    g_x1);
    cudaGetSymbolAddress((void**)&bqkv,   g_bqkv);

    cudaFuncSetAttribute(attn_kernel,  cudaFuncAttributeMaxDynamicSharedMemorySize, ATTN_SMEM_BYTES);
    cudaFuncSetAttribute(gemm_f16,     cudaFuncAttributeMaxDynamicSharedMemorySize, GEMM_SMEM_BYTES);
    cudaFuncSetAttribute(gemm_f16_o16, cudaFuncAttributeMaxDynamicSharedMemorySize, GEMM_SMEM_BYTES);

    // 0. weight conversion / packing
    {
        const int T = 256;
        cvt16_kernel<<<(2048*2048/8 + T-1)/T, T>>>(wq, wqkv16,                 2048*2048/8);
        cvt16_kernel<<<( 512*2048/8 + T-1)/T, T>>>(wk, wqkv16 + 2048*2048,      512*2048/8);
        cvt16_kernel<<<( 512*2048/8 + T-1)/T, T>>>(wv, wqkv16 + 2560*2048,      512*2048/8);
        cvt16_kernel<<<(2048*2048/8 + T-1)/T, T>>>(wo, wo16,                   2048*2048/8);
        cvt16_kernel<<<(8192*2048/8 + T-1)/T, T>>>(wg, wgu16,                  8192*2048/8);
        cvt16_kernel<<<(8192*2048/8 + T-1)/T, T>>>(wu, wgu16 + 8192*2048,      8192*2048/8);
        cvt16_kernel<<<(2048*8192/8 + T-1)/T, T>>>(wd, wd16,                   2048*8192/8);
        pack_bias_kernel<<<(QKV_LD + T-1)/T, T>>>(bq, bk, bv, bqkv);
    }

    // 1. h16 = (half) RMSNorm(x, ln1)
    rmsnorm16_kernel<<<TTOK, 256>>>(x, ln1, h16);
    // 2. packed QKV projection
    gemm_f16<<<dim3(QKV_LD/128, TTOK/128), 256, GEMM_SMEM_BYTES>>>(h16, wqkv16, bqkv, nullptr, qkv_, QKV_LD, HIDN);
    // 3. per-head RMSNorm + RoPE (in place, packed)
    qknorm_rope_kernel<<<dim3(TTOK, NH + NKV), 128>>>(qkv_, qnw, knw, cosb, sinb);
    // 4. causal flash attention (fp16 MMA) -> fp16
    attn_kernel<<<dim3(SEQ/64, NH, BATCH), 256, ATTN_SMEM_BYTES>>>(qkv_, attn16);
    // 5. x1 = x + attn @ wo^T
    gemm_f16<<<dim3(HIDN/128, TTOK/128), 256, GEMM_SMEM_BYTES>>>(attn16, wo16, nullptr, x, x1_, HIDN, HIDN);
    // 6. h16 = (half) RMSNorm(x1, ln2)
    rmsnorm16_kernel<<<TTOK, 256>>>(x1_, ln2, h16);
    // 7. gate|up projection -> fp16
    gemm_f16_o16<<<dim3(2*INTERN/128, TTOK/128), 256, GEMM_SMEM_BYTES>>>(h16, wgu16, gu16, 2*INTERN, HIDN);
    // 8. act16 = (half)(silu(gate) * up)
    silu16_kernel<<<TTOK*INTERN/8/256, 256>>>(gu16, act16, TTOK*INTERN/8);
    // 9. out = x1 + act @ wd^T
    gemm_f16<<<dim3(HIDN/128, TTOK/128), 256, GEMM_SMEM_BYTES>>>(act16, wd16, nullptr, x1_, out, HIDN, INTERN);
}

// round 13
// speedup vs baseline: 2.0244x; 1.0117x over previous
#include <cuda_runtime.h>
#include <cuda_fp16.h>
#include <cstdint>

#define HIDN   2048
#define NH     16
#define NKV    4
#define HD     128
#define INTERN 8192
#define BATCH  4
#define SEQ    1024
#define TTOK   (BATCH*SEQ)
#define EPSV   1e-6f
#define QK_SCALE 0.08838834764831845f
#define QKV_LD (NH*HD + 2*NKV*HD)      /* 3072 */

// ---------------- scratch ----------------
__device__ __half g_h16   [TTOK * HIDN];
__device__ __half g_qkv16 [TTOK * QKV_LD];
__device__ __half g_attn16[TTOK * HIDN];
__device__ float  g_x1    [TTOK * HIDN];
__device__ __half g_act16 [TTOK * INTERN];
__device__ __half g_wqkv16[QKV_LD * HIDN];
__device__ __half g_wo16  [HIDN * HIDN];
__device__ __half g_wgu16 [2 * INTERN * HIDN];   // row-interleaved: g_j->2j, u_j->2j+1
__device__ __half g_wd16  [HIDN * INTERN];
__device__ float  g_bqkv  [QKV_LD];

// ---------------- helpers ----------------
__device__ __forceinline__ void mma_f16(float c[4], const uint32_t a[4], const uint32_t b[2]) {
    asm volatile("mma.sync.aligned.m16n8k16.row.col.f32.f16.f16.f32 "
        "{%0,%1,%2,%3}, {%4,%5,%6,%7}, {%8,%9}, {%0,%1,%2,%3};\n"
        : "+f"(c[0]), "+f"(c[1]), "+f"(c[2]), "+f"(c[3])
        : "r"(a[0]), "r"(a[1]), "r"(a[2]), "r"(a[3]), "r"(b[0]), "r"(b[1]));
}
__device__ __forceinline__ uint32_t pack_h2(float lo, float hi) {
    __half2 h = __floats2half2_rn(lo, hi);
    return *(uint32_t*)&h;
}

#define CP16(dst, src) \
    asm volatile("cp.async.cg.shared.global [%0], [%1], 16;" :: "r"(dst), "l"(src))
#define CP_COMMIT() asm volatile("cp.async.commit_group;")
#define CP_WAIT(n)  asm volatile("cp.async.wait_group %0;" :: "n"(n))

// ---------------- fp16 GEMM, cp.async 4-stage ----------------
// MODE 0: float C (+bias)(+res). MODE 1: half C (+bias). MODE 2: half C = silu/up pair fuse.
#define STAGES 4
#define STAGE_BYTES 20480
#define GEMM_SMEM_BYTES (STAGES * STAGE_BYTES)

template<int MODE>
__device__ __forceinline__ void gemm_core(
    const __half* __restrict__ A, const __half* __restrict__ B,
    const float* __restrict__ bias, const float* __restrict__ res,
    void* __restrict__ Cv, int ldc, int K)
{
    extern __shared__ uint8_t smem_raw[];
    const int tid  = threadIdx.x;
    const int lane = tid & 31, warp = tid >> 5;
    const int wm = warp & 1, wn = warp >> 1;
    const int g  = lane >> 2, t4 = lane & 3;
    const int brow = blockIdx.y << 7, bcol = blockIdx.x << 7;

    const int ar = tid >> 2, achk = tid & 3;
    const __half* ag0 = A + (size_t)(brow + ar) * K + achk * 8;
    const __half* ag1 = ag0 + (size_t)64 * K;
    const __half* bg0 = B + (size_t)(bcol + ar) * K + achk * 8;
    const __half* bg1 = bg0 + (size_t)64 * K;

    const uint32_t sbase = (uint32_t)__cvta_generic_to_shared(smem_raw);
    const uint32_t sA0 = ar * 80 + achk * 16;
    const uint32_t sA1 = sA0 + 64 * 80;
    const uint32_t sB0 = 10240 + sA0;
    const uint32_t sB1 = 10240 + sA1;

    float acc[4][4][4];
#pragma unroll
    for (int i = 0; i < 4; i++)
#pragma unroll
        for (int j = 0; j < 4; j++)
#pragma unroll
            for (int e = 0; e < 4; e++) acc[i][j][e] = 0.f;

    const int nk = K >> 5;

#pragma unroll
    for (int s = 0; s < STAGES - 1; ++s) {
        uint32_t st = sbase + s * STAGE_BYTES;
        CP16(st + sA0, ag0 + s * 32);
        CP16(st + sA1, ag1 + s * 32);
        CP16(st + sB0, bg0 + s * 32);
        CP16(st + sB1, bg1 + s * 32);
        CP_COMMIT();
    }

    for (int t = 0; t < nk; ++t) {
        CP_WAIT(STAGES - 2);
        __syncthreads();
        const int tn = t + STAGES - 1;
        if (tn < nk) {
            uint32_t st = sbase + (tn & (STAGES - 1)) * STAGE_BYTES;
            CP16(st + sA0, ag0 + tn * 32);
            CP16(st + sA1, ag1 + tn * 32);
            CP16(st + sB0, bg0 + tn * 32);
            CP16(st + sB1, bg1 + tn * 32);
            CP_COMMIT();
        }
        const uint32_t* As_ = (const uint32_t*)(smem_raw + (t & (STAGES - 1)) * STAGE_BYTES);
        const uint32_t* Bs_ = As_ + 2560;
#pragma unroll
        for (int kb = 0; kb < 16; kb += 8) {
            uint32_t af[4][4], bf[4][2];
#pragma unroll
            for (int mt = 0; mt < 4; ++mt) {
                int base = (wm * 64 + mt * 16 + g) * 20 + kb + t4;
                af[mt][0] = As_[base];
                af[mt][1] = As_[base + 160];
                af[mt][2] = As_[base + 4];
                af[mt][3] = As_[base + 164];
            }
#pragma unroll
            for (int nt = 0; nt < 4; ++nt) {
                int nbase = (wn * 32 + nt * 8 + g) * 20 + kb + t4;
                bf[nt][0] = Bs_[nbase];
                bf[nt][1] = Bs_[nbase + 4];
            }
#pragma unroll
            for (int mt = 0; mt < 4; ++mt)
#pragma unroll
                for (int nt = 0; nt < 4; ++nt)
                    mma_f16(acc[mt][nt], af[mt], bf[nt]);
        }
    }

#pragma unroll
    for (int mt = 0; mt < 4; ++mt) {
        int r0 = brow + wm * 64 + mt * 16 + g;
#pragma unroll
        for (int nt = 0; nt < 4; ++nt) {
            int c0 = bcol + wn * 32 + nt * 8 + t4 * 2;
            float2 v0 = make_float2(acc[mt][nt][0], acc[mt][nt][1]);
            float2 v1 = make_float2(acc[mt][nt][2], acc[mt][nt][3]);
            if (MODE == 2) {
                // interleaved cols: (v.x, v.y) = (gate_j, up_j), j = c0/2
                __half* A16 = (__half*)Cv;
                int j0 = c0 >> 1;
                float a0 = v0.x / (1.f + __expf(-v0.x)) * v0.y;
                float a1 = v1.x / (1.f + __expf(-v1.x)) * v1.y;
                A16[(size_t)r0 * ldc + j0]       = __float2half(a0);
                A16[(size_t)(r0 + 8) * ldc + j0] = __float2half(a1);
            } else {
                if (bias) {
                    float2 bv = *(const float2*)&bias[c0];
                    v0.x += bv.x; v0.y += bv.y; v1.x += bv.x; v1.y += bv.y;
                }
                if (MODE == 1) {
                    __half* C16 = (__half*)Cv;
                    *(uint32_t*)&C16[(size_t)r0 * ldc + c0]       = pack_h2(v0.x, v0.y);
                    *(uint32_t*)&C16[(size_t)(r0 + 8) * ldc + c0] = pack_h2(v1.x, v1.y);
                } else {
                    float* C = (float*)Cv;
                    if (res) {
                        float2 ra = *(const float2*)&res[(size_t)r0 * ldc + c0];
                        float2 rb = *(const float2*)&res[(size_t)(r0 + 8) * ldc + c0];
                        v0.x += ra.x; v0.y += ra.y; v1.x += rb.x; v1.y += rb.y;
                    }
                    *(float2*)&C[(size_t)r0 * ldc + c0]       = v0;
                    *(float2*)&C[(size_t)(r0 + 8) * ldc + c0] = v1;
                }
            }
        }
    }
}

__global__ __launch_bounds__(256, 2)
void gemm_f16(const __half* __restrict__ A, const __half* __restrict__ B,
              const float* __restrict__ bias, const float* __restrict__ res,
              float* __restrict__ C, int ldc, int K) {
    gemm_core<0>(A, B, bias, res, C, ldc, K);
}
__global__ __launch_bounds__(256, 2)
void gemm_f16_qkv(const __half* __restrict__ A, const __half* __restrict__ B,
                  const float* __restrict__ bias, __half* __restrict__ C, int ldc, int K) {
    gemm_core<1>(A, B, bias, nullptr, C, ldc, K);
}
__global__ __launch_bounds__(256, 2)
void gemm_f16_silu(const __half* __restrict__ A, const __half* __restrict__ B,
                   __half* __restrict__ C, int ldc, int K) {
    gemm_core<2>(A, B, nullptr, nullptr, C, ldc, K);
}

// ---------------- fp32 -> fp16 convert, 16 elems/thread ----------------
__global__ void cvt16_kernel(const float* __restrict__ src, __half* __restrict__ dst, int n16) {
    int i = blockIdx.x * blockDim.x + threadIdx.x;
    if (i >= n16) return;
#pragma unroll
    for (int h = 0; h < 2; h++) {
        float4 a = ((const float4*)src)[4 * i + 2 * h];
        float4 b = ((const float4*)src)[4 * i + 2 * h + 1];
        uint4 o;
        o.x = pack_h2(a.x, a.y); o.y = pack_h2(a.z, a.w);
        o.z = pack_h2(b.x, b.y); o.w = pack_h2(b.z, b.w);
        ((uint4*)dst)[2 * i + h] = o;
    }
}
// interleaved for gate/up: src row j -> dst row 2j+off. Kc = K/8 chunks per row.
__global__ void cvt16_il_kernel(const float* __restrict__ src, __half* __restrict__ dst,
                                int Kc, int off, int n8) {
    int i = blockIdx.x * blockDim.x + threadIdx.x;
    if (i >= n8) return;
    int row = i / Kc, cj = i - row * Kc;
    float4 a = ((const float4*)src)[2 * i];
    float4 b = ((const float4*)src)[2 * i + 1];
    uint4 o;
    o.x = pack_h2(a.x, a.y); o.y = pack_h2(a.z, a.w);
    o.z = pack_h2(b.x, b.y); o.w = pack_h2(b.z, b.w);
    ((uint4*)dst)[(size_t)(2 * row + off) * Kc + cj] = o;
}

__global__ void pack_bias_kernel(const float* __restrict__ bq, const float* __restrict__ bk,
                                 const float* __restrict__ bv, float* __restrict__ dst) {
    int i = blockIdx.x * blockDim.x + threadIdx.x;
    if (i < QKV_LD)
        dst[i] = (i < 2048) ? bq[i] : ((i < 2560) ? bk[i - 2048] : bv[i - 2560]);
}

// ---------------- RMSNorm -> fp16 ----------------
__global__ void rmsnorm16_kernel(const float* __restrict__ x, const float* __restrict__ w,
                                 __half* __restrict__ out) {
    int row = blockIdx.x;
    const float* xr = x + (size_t)row * HIDN;
    float4 v[2];
    float ss = 0.f;
#pragma unroll
    for (int i = 0; i < 2; i++) {
        v[i] = *(const float4*)&xr[(threadIdx.x + i * 256) * 4];
        ss += v[i].x * v[i].x + v[i].y * v[i].y + v[i].z * v[i].z + v[i].w * v[i].w;
    }
#pragma unroll
    for (int o = 16; o; o >>= 1) ss += __shfl_xor_sync(~0u, ss, o);
    __shared__ float red[8];
    if ((threadIdx.x & 31) == 0) red[threadIdx.x >> 5] = ss;
    __syncthreads();
    if (threadIdx.x == 0) {
        float t = 0.f;
#pragma unroll
        for (int i = 0; i < 8; i++) t += red[i];
        red[0] = rsqrtf(t / (float)HIDN + EPSV);
    }
    __syncthreads();
    float r = red[0];
#pragma unroll
    for (int i = 0; i < 2; i++) {
        int c = (threadIdx.x + i * 256) * 4;
        float4 wv = *(const float4*)&w[c];
        uint2 o2;
        o2.x = pack_h2(v[i].x * r * wv.x, v[i].y * r * wv.y);
        o2.y = pack_h2(v[i].z * r * wv.z, v[i].w * r * wv.w);
        *(uint2*)&out[(size_t)row * HIDN + c] = o2;
    }
}

// ---------------- per-head RMSNorm + RoPE on fp16 qkv (q pre-scaled) ----------------
__global__ void qknorm_rope16_kernel(__half* __restrict__ qkv,
                                     const float* __restrict__ qw, const float* __restrict__ kw,
                                     const float* __restrict__ cs, const float* __restrict__ sn) {
    int token = blockIdx.x, h = blockIdx.y;
    __half* p; const float* w; float oscale;
    if (h < NH) { p = qkv + (size_t)token * QKV_LD + h * HD;               w = qw; oscale = QK_SCALE; }
    else        { p = qkv + (size_t)token * QKV_LD + 2048 + (h - NH) * HD; w = kw; oscale = 1.f; }
    int d = threadIdx.x;
    float v = __half2float(p[d]);
    float ss = v * v;
#pragma unroll
    for (int o = 16; o; o >>= 1) ss += __shfl_xor_sync(~0u, ss, o);
    __shared__ float red[4];
    __shared__ float sh[128];
    if ((d & 31) == 0) red[d >> 5] = ss;
    __syncthreads();
    float tot = red[0] + red[1] + red[2] + red[3];
    float r = rsqrtf(tot / 128.f + EPSV);
    float xn = v * r * w[d];
    sh[d] = xn;
    __syncthreads();
    float rot = (d < 64) ? -sh[d + 64] : sh[d - 64];
    float c = cs[(size_t)token * 128 + d], s = sn[(size_t)token * 128 + d];
    p[d] = __float2half((xn * c + rot * s) * oscale);
}

// ---------------- flash attention (fp16 MMA, fp16 qkv input, causal, GQA) ----------------
#define AQK_STRIDE 68
#define AV_STRIDE  136
#define AP_STRIDE  36
#define ATTN_U32  (2 * 64 * AQK_STRIDE + 32 * AV_STRIDE + 64 * AP_STRIDE + 2*64 + 2*64 + 3*64)
#define ATTN_SMEM_BYTES (ATTN_U32 * 4)

__global__ __launch_bounds__(256, 2)
void attn_kernel(const __half* __restrict__ qkv, __half* __restrict__ o16) {
    extern __shared__ uint32_t smem[];
    uint32_t* Qs = smem;
    uint32_t* Ks = Qs + 64 * AQK_STRIDE;
    uint32_t* Vs = Ks + 64 * AQK_STRIDE;
    uint32_t* Ps = Vs + 32 * AV_STRIDE;
    float* Pmax = (float*)(Ps + 64 * AP_STRIDE);
    float* Psum = Pmax + 128;
    float* Mrow = Psum + 128;
    float* Lrow = Mrow + 64;
    float* Arow = Lrow + 64;

    const int tid  = threadIdx.x;
    const int lane = tid & 31, warp = tid >> 5;
    const int wm = warp & 3, wn = warp >> 2;
    const int g = lane >> 2, t4 = lane & 3;
    const int qt = blockIdx.x, hq = blockIdx.y, b = blockIdx.z;
    const int kvh = hq >> 2;
    const int tok0 = b * SEQ + qt * 64;
    const int r0 = wm * 16 + g, r1 = r0 + 8;

    // Q tile: raw uint4 copy (pre-scaled fp16), 64 rows x 16 chunks
    for (int l = tid; l < 64 * 16; l += 256) {
        int r = l >> 4, c = (l & 15);
        uint4 qv = *(const uint4*)&qkv[(size_t)(tok0 + r) * QKV_LD + hq * HD + c * 8];
        *(uint4*)&Qs[r * AQK_STRIDE + c * 4] = qv;
    }
    if (tid < 64) { Mrow[tid] = -3.0e38f; Lrow[tid] = 0.f; }

    float O[8][4];
#pragma unroll
    for (int nt = 0; nt < 8; nt++)
#pragma unroll
        for (int e = 0; e < 4; e++) O[nt][e] = 0.f;
    __syncthreads();

    for (int kt = 0; kt <= qt; ++kt) {
        for (int l = tid; l < 64 * 16; l += 256) {
            int r = l >> 4, c = (l & 15);
            uint4 kv = *(const uint4*)&qkv[(size_t)(b * SEQ + kt * 64 + r) * QKV_LD + 2048 + kvh * HD + c * 8];
            *(uint4*)&Ks[r * AQK_STRIDE + c * 4] = kv;
        }
        // V tile: k-pair interleave via prmt, 32 packed rows x 16 chunks
        for (int l = tid; l < 32 * 16; l += 256) {
            int r = l >> 4, c = (l & 15);
            size_t base = (size_t)(b * SEQ + kt * 64 + 2 * r) * QKV_LD + 2560 + kvh * HD + c * 8;
            uint4 va = *(const uint4*)&qkv[base];
            uint4 vb = *(const uint4*)&qkv[base + QKV_LD];
            uint4 o0, o1;
            o0.x = __byte_perm(va.x, vb.x, 0x5410); o0.y = __byte_perm(va.x, vb.x, 0x7632);
            o0.z = __byte_perm(va.y, vb.y, 0x5410); o0.w = __byte_perm(va.y, vb.y, 0x7632);
            o1.x = __byte_perm(va.z, vb.z, 0x5410); o1.y = __byte_perm(va.z, vb.z, 0x7632);
            o1.z = __byte_perm(va.w, vb.w, 0x5410); o1.w = __byte_perm(va.w, vb.w, 0x7632);
            *(uint4*)&Vs[r * AV_STRIDE + c * 8]     = o0;
            *(uint4*)&Vs[r * AV_STRIDE + c * 8 + 4] = o1;
        }
        __syncthreads();

        float s[4][4];
#pragma unroll
        for (int nt = 0; nt < 4; nt++)
#pragma unroll
            for (int e = 0; e < 4; e++) s[nt][e] = 0.f;
        {
            const int arow0 = r0 * AQK_STRIDE, arow1 = r1 * AQK_STRIDE;
#pragma unroll
            for (int kb = 0; kb < 64; kb += 8) {
                uint32_t a[4];
                a[0] = Qs[arow0 + kb + t4];
                a[1] = Qs[arow1 + kb + t4];
                a[2] = Qs[arow0 + kb + t4 + 4];
                a[3] = Qs[arow1 + kb + t4 + 4];
#pragma unroll
                for (int nt = 0; nt < 4; nt++) {
                    uint32_t bb[2];
                    int nb = (wn * 32 + nt * 8 + g) * AQK_STRIDE + kb + t4;
                    bb[0] = Ks[nb]; bb[1] = Ks[nb + 4];
                    mma_f16(s[nt], a, bb);
                }
            }
        }

        if (kt == qt) {
#pragma unroll
            for (int nt = 0; nt < 4; nt++) {
                int c0 = wn * 32 + nt * 8 + 2 * t4;
                if (c0     > r0) s[nt][0] = -1.0e30f;
                if (c0 + 1 > r0) s[nt][1] = -1.0e30f;
                if (c0     > r1) s[nt][2] = -1.0e30f;
                if (c0 + 1 > r1) s[nt][3] = -1.0e30f;
            }
        }

        {
            float mx0 = fmaxf(fmaxf(s[0][0], s[0][1]), fmaxf(s[1][0], s[1][1]));
            mx0 = fmaxf(mx0, fmaxf(fmaxf(s[2][0], s[2][1]), fmaxf(s[3][0], s[3][1])));
            float mx1 = fmaxf(fmaxf(s[0][2], s[0][3]), fmaxf(s[1][2], s[1][3]));
            mx1 = fmaxf(mx1, fmaxf(fmaxf(s[2][2], s[2][3]), fmaxf(s[3][2], s[3][3])));
            mx0 = fmaxf(mx0, __shfl_xor_sync(~0u, mx0, 1));
            mx0 = fmaxf(mx0, __shfl_xor_sync(~0u, mx0, 2));
            mx1 = fmaxf(mx1, __shfl_xor_sync(~0u, mx1, 1));
            mx1 = fmaxf(mx1, __shfl_xor_sync(~0u, mx1, 2));
            if (t4 == 0) { Pmax[wn * 64 + r0] = mx0; Pmax[wn * 64 + r1] = mx1; }
        }
        __syncthreads();

        {
            float mn0 = fmaxf(Mrow[r0], fmaxf(Pmax[r0], Pmax[64 + r0]));
            float mn1 = fmaxf(Mrow[r1], fmaxf(Pmax[r1], Pmax[64 + r1]));
            float sum0 = 0.f, sum1 = 0.f;
#pragma unroll
            for (int nt = 0; nt < 4; nt++) {
                int cu = wn * 16 + nt * 4 + t4;
                float p0 = __expf(s[nt][0] - mn0);
                float p1 = __expf(s[nt][1] - mn0);
                float p2 = __expf(s[nt][2] - mn1);
                float p3 = __expf(s[nt][3] - mn1);
                sum0 += p0 + p1; sum1 += p2 + p3;
                Ps[r0 * AP_STRIDE + cu] = pack_h2(p0, p1);
                Ps[r1 * AP_STRIDE + cu] = pack_h2(p2, p3);
            }
            sum0 += __shfl_xor_sync(~0u, sum0, 1);
            sum0 += __shfl_xor_sync(~0u, sum0, 2);
            sum1 += __shfl_xor_sync(~0u, sum1, 1);
            sum1 += __shfl_xor_sync(~0u, sum1, 2);
            if (t4 == 0) { Psum[wn * 64 + r0] = sum0; Psum[wn * 64 + r1] = sum1; }
        }
        __syncthreads();

        if (tid < 64) {
            int r = tid;
            float mo = Mrow[r];
            float mn = fmaxf(mo, fmaxf(Pmax[r], Pmax[64 + r]));
            float al = __expf(mo - mn);
            Lrow[r] = Lrow[r] * al + Psum[r] + Psum[64 + r];
            Mrow[r] = mn;
            Arow[r] = al;
        }
        __syncthreads();

        {
            float al0 = Arow[r0], al1 = Arow[r1];
#pragma unroll
            for (int nt = 0; nt < 8; nt++) {
                O[nt][0] *= al0; O[nt][1] *= al0;
                O[nt][2] *= al1; O[nt][3] *= al1;
            }
            const int prow0 = r0 * AP_STRIDE, prow1 = r1 * AP_STRIDE;
#pragma unroll
            for (int kb = 0; kb < 32; kb += 8) {
                uint32_t a[4];
                a[0] = Ps[prow0 + kb + t4];
                a[1] = Ps[prow1 + kb + t4];
                a[2] = Ps[prow0 + kb + t4 + 4];
                a[3] = Ps[prow1 + kb + t4 + 4];
#pragma unroll
                for (int nt = 0; nt < 8; nt++) {
                    uint32_t bb[2];
                    int col = wn * 64 + nt * 8 + g;
                    bb[0] = Vs[(kb + t4) * AV_STRIDE + col];
                    bb[1] = Vs[(kb + t4 + 4) * AV_STRIDE + col];
                    mma_f16(O[nt], a, bb);
                }
            }
        }
        __syncthreads();
    }

    {
        float inv0 = 1.f / Lrow[r0], inv1 = 1.f / Lrow[r1];
        size_t base0 = (size_t)(tok0 + r0) * (NH * HD) + hq * HD;
        size_t base1 = (size_t)(tok0 + r1) * (NH * HD) + hq * HD;
#pragma unroll
        for (int nt = 0; nt < 8; nt++) {
            int c = wn * 64 + nt * 8 + 2 * t4;
            *(uint32_t*)&o16[base0 + c] = pack_h2(O[nt][0] * inv0, O[nt][1] * inv0);
            *(uint32_t*)&o16[base1 + c] = pack_h2(O[nt][2] * inv1, O[nt][3] * inv1);
        }
    }
}

// ---------------- host orchestration ----------------
extern "C" void kernel_launch(void* const* d_in, const int* in_sizes, int n_in,
                              void* d_out, int out_size) {
    const float* x    = (const float*)d_in[0];
    const float* cosb = (const float*)d_in[2];
    const float* sinb = (const float*)d_in[3];
    const float* wq   = (const float*)d_in[4];
    const float* bq   = (const float*)d_in[5];
    const float* wk   = (const float*)d_in[6];
    const float* bk   = (const float*)d_in[7];
    const float* wv   = (const float*)d_in[8];
    const float* bv   = (const float*)d_in[9];
    const float* wo   = (const float*)d_in[10];
    const float* qnw  = (const float*)d_in[11];
    const float* knw  = (const float*)d_in[12];
    const float* ln1  = (const float*)d_in[13];
    const float* ln2  = (const float*)d_in[14];
    const float* wg   = (const float*)d_in[15];
    const float* wu   = (const float*)d_in[16];
    const float* wd   = (const float*)d_in[17];
    float* out = (float*)d_out;

    __half *h16, *attn16, *act16, *wqkv16, *wo16, *wgu16, *wd16, *qkv16;
    float *x1_, *bqkv;
    cudaGetSymbolAddress((void**)&h16,    g_h16);
    cudaGetSymbolAddress((void**)&attn16, g_attn16);
    cudaGetSymbolAddress((void**)&act16,  g_act16);
    cudaGetSymbolAddress((void**)&wqkv16, g_wqkv16);
    cudaGetSymbolAddress((void**)&wo16,   g_wo16);
    cudaGetSymbolAddress((void**)&wgu16,  g_wgu16);
    cudaGetSymbolAddress((void**)&wd16,   g_wd16);
    cudaGetSymbolAddress((void**)&qkv16,  g_qkv16);
    cudaGetSymbolAddress((void**)&x1_,    g_x1);
    cudaGetSymbolAddress((void**)&bqkv,   g_bqkv);

    cudaFuncSetAttribute(attn_kernel,   cudaFuncAttributeMaxDynamicSharedMemorySize, ATTN_SMEM_BYTES);
    cudaFuncSetAttribute(gemm_f16,      cudaFuncAttributeMaxDynamicSharedMemorySize, GEMM_SMEM_BYTES);
    cudaFuncSetAttribute(gemm_f16_qkv,  cudaFuncAttributeMaxDynamicSharedMemorySize, GEMM_SMEM_BYTES);
    cudaFuncSetAttribute(gemm_f16_silu, cudaFuncAttributeMaxDynamicSharedMemorySize, GEMM_SMEM_BYTES);

    // 0. weight conversion / packing
    {
        const int T = 256;
        cvt16_kernel<<<(2048*2048/16 + T-1)/T, T>>>(wq, wqkv16,              2048*2048/16);
        cvt16_kernel<<<( 512*2048/16 + T-1)/T, T>>>(wk, wqkv16 + 2048*2048,   512*2048/16);
        cvt16_kernel<<<( 512*2048/16 + T-1)/T, T>>>(wv, wqkv16 + 2560*2048,   512*2048/16);
        cvt16_kernel<<<(2048*2048/16 + T-1)/T, T>>>(wo, wo16,                2048*2048/16);
        cvt16_il_kernel<<<(8192*2048/8 + T-1)/T, T>>>(wg, wgu16, 2048/8, 0,  8192*2048/8);
        cvt16_il_kernel<<<(8192*2048/8 + T-1)/T, T>>>(wu, wgu16, 2048/8, 1,  8192*2048/8);
        cvt16_kernel<<<(2048*8192/16 + T-1)/T, T>>>(wd, wd16,                2048*8192/16);
        pack_bias_kernel<<<(QKV_LD + T-1)/T, T>>>(bq, bk, bv, bqkv);
    }

    // 1. h16 = (half) RMSNorm(x, ln1)
    rmsnorm16_kernel<<<TTOK, 256>>>(x, ln1, h16);
    // 2. packed QKV projection -> fp16
    gemm_f16_qkv<<<dim3(QKV_LD/128, TTOK/128), 256, GEMM_SMEM_BYTES>>>(h16, wqkv16, bqkv, qkv16, QKV_LD, HIDN);
    // 3. per-head RMSNorm + RoPE (fp16, q pre-scaled by 1/sqrt(d))
    qknorm_rope16_kernel<<<dim3(TTOK, NH + NKV), 128>>>(qkv16, qnw, knw, cosb, sinb);
    // 4. causal flash attention (fp16 in / fp16 MMA / fp16 out)
    attn_kernel<<<dim3(SEQ/64, NH, BATCH), 256, ATTN_SMEM_BYTES>>>(qkv16, attn16);
    // 5. x1 = x + attn @ wo^T
    gemm_f16<<<dim3(HIDN/128, TTOK/128), 256, GEMM_SMEM_BYTES>>>(attn16, wo16, nullptr, x, x1_, HIDN, HIDN);
    // 6. h16 = (half) RMSNorm(x1, ln2)
    rmsnorm16_kernel<<<TTOK, 256>>>(x1_, ln2, h16);
    // 7. fused gate|up projection + silu (interleaved weights) -> act16
    gemm_f16_silu<<<dim3(2*INTERN/128, TTOK/128), 256, GEMM_SMEM_BYTES>>>(h16, wgu16, act16, INTERN, HIDN);
    // 8. out = x1 + act @ wd^T
    gemm_f16<<<dim3(HIDN/128, TTOK/128), 256, GEMM_SMEM_BYTES>>>(act16, wd16, nullptr, x1_, out, HIDN, INTERN);
}